// round 1
// baseline (speedup 1.0000x reference)
#include <cuda_runtime.h>
#include <math.h>
#include <float.h>

#define NTOK 4096
#define DIM  512
#define RH_  256
#define G_   8
#define S_   4
#define E_   32
#define FE_  64
#define DH_  256
#define SHARP_ 16.0f

// ---------------- scratch (device globals; no allocation) ----------------
__device__ float    g_GH[NTOK * RH_];        // gelu(H@Wr1+br1)
__device__ int      g_cnt[E_];               // tokens per expert
__device__ int      g_tok[E_ * NTOK];        // gathered token ids per expert
__device__ float    g_wt [E_ * NTOK];        // gathered weights per expert
__device__ unsigned g_minenc, g_maxenc;      // order-preserving encoded feat min/max

__device__ __forceinline__ unsigned encf(float x) {
    unsigned u = __float_as_uint(x);
    return (u & 0x80000000u) ? ~u : (u | 0x80000000u);
}
__device__ __forceinline__ float decf(unsigned e) {
    return (e & 0x80000000u) ? __uint_as_float(e ^ 0x80000000u)
                             : __uint_as_float(~e);
}
__device__ __forceinline__ float gelu_exact(float x) {
    return 0.5f * x * (1.0f + erff(x * 0.70710678118654752f));
}

// ---------------- K0a: reset ----------------
__global__ void k_reset() {
    int i = threadIdx.x;
    if (i < E_) g_cnt[i] = 0;
    if (i == 0) { g_minenc = 0xFFFFFFFFu; g_maxenc = 0u; }
}

// ---------------- K0b: feat global min/max ----------------
__global__ void k_minmax(const float* __restrict__ feat, int n) {
    unsigned lmin = 0xFFFFFFFFu, lmax = 0u;
    for (int i = blockIdx.x * blockDim.x + threadIdx.x; i < n; i += gridDim.x * blockDim.x) {
        unsigned e = encf(feat[i]);
        lmin = min(lmin, e); lmax = max(lmax, e);
    }
    #pragma unroll
    for (int o = 16; o; o >>= 1) {
        lmin = min(lmin, __shfl_down_sync(0xFFFFFFFFu, lmin, o));
        lmax = max(lmax, __shfl_down_sync(0xFFFFFFFFu, lmax, o));
    }
    if ((threadIdx.x & 31) == 0) {
        atomicMin(&g_minenc, lmin);
        atomicMax(&g_maxenc, lmax);
    }
}

// ---------------- K1: GH = gelu(H @ Wr1 + br1)  [4096,512]x[512,256] ----------------
__global__ __launch_bounds__(256) void k_gemm1(const float* __restrict__ H,
                                               const float* __restrict__ Wr1,
                                               const float* __restrict__ br1) {
    __shared__ __align__(16) float Xs[64][36];
    const int h = threadIdx.x;            // output column 0..255
    const int base = blockIdx.x * 32;     // 32 tokens per block
    float acc[32];
    #pragma unroll
    for (int t = 0; t < 32; t++) acc[t] = 0.f;

    for (int kc = 0; kc < DIM; kc += 64) {
        #pragma unroll
        for (int it = 0; it < 8; it++) {
            int idx = it * 256 + h;
            int t = idx >> 6, j = idx & 63;
            Xs[j][t] = H[(size_t)(base + t) * DIM + kc + j];
        }
        __syncthreads();
        #pragma unroll 8
        for (int d = 0; d < 64; d++) {
            float wv = Wr1[(size_t)(kc + d) * RH_ + h];
            const float4* xr = (const float4*)Xs[d];
            #pragma unroll
            for (int q = 0; q < 8; q++) {
                float4 xv = xr[q];
                acc[4*q+0] += xv.x * wv; acc[4*q+1] += xv.y * wv;
                acc[4*q+2] += xv.z * wv; acc[4*q+3] += xv.w * wv;
            }
        }
        __syncthreads();
    }
    float b = br1[h];
    #pragma unroll
    for (int t = 0; t < 32; t++)
        g_GH[(size_t)(base + t) * RH_ + h] = gelu_exact(acc[t] + b);
}

// ---------------- K2: per-token routing ----------------
__global__ __launch_bounds__(256) void k_route(
    const float* __restrict__ H,   const float* __restrict__ feat,
    const float* __restrict__ Wr2, const float* __restrict__ br2,
    const float* __restrict__ Wfe, const float* __restrict__ bfe,
    const float* __restrict__ Win_h, const float* __restrict__ Win_f,
    const float* __restrict__ bin_b, const float* __restrict__ be2,
    float* __restrict__ y)
{
    __shared__ float hs[512], ghs[256], feat_s[32], femb_s[512];
    __shared__ float glog_s[8], ilog_s[32], score_s[8], gw_s[8], cw_s[32], w_s[32];

    const int t = blockIdx.x, tid = threadIdx.x;
    const int wid = tid >> 5, lane = tid & 31;

    hs[tid]        = H[(size_t)t * 512 + tid];
    hs[tid + 256]  = H[(size_t)t * 512 + tid + 256];
    ghs[tid]       = g_GH[(size_t)t * 256 + tid];
    if (tid < 32) feat_s[tid] = feat[(size_t)t * 32 + tid];
    __syncthreads();

    // glog[g]: warp g does 256-dot
    {
        float p = 0.f;
        #pragma unroll
        for (int k = 0; k < 8; k++) {
            int i = lane + 32 * k;
            p += ghs[i] * Wr2[i * 8 + wid];
        }
        #pragma unroll
        for (int o = 16; o; o >>= 1) p += __shfl_down_sync(0xFFFFFFFFu, p, o);
        if (lane == 0) glog_s[wid] = p + br2[wid];   // TEMP=1
    }

    // score[g] = mean_f to_ratio(feat)
    const bool in01 = (decf(g_minenc) >= -1e-6f) && (decf(g_maxenc) <= 1.0f + 1e-6f);
    if (tid < 8) {
        float sc = 0.f;
        #pragma unroll
        for (int f = 0; f < 4; f++) {
            float x = feat_s[tid * 4 + f];
            float r = in01 ? fminf(fmaxf(x, 0.f), 1.f)
                           : fminf(fmaxf(0.5f * (1.f + erff(x * 0.70710678118654752f)), 0.f), 1.f);
            sc += r;
        }
        score_s[tid] = sc * 0.25f;
    }

    // femb[g][e] = feat_g @ Wfe + bfe
    #pragma unroll
    for (int o = tid; o < 512; o += 256) {
        int g = o >> 6, e2 = o & 63;
        float v = bfe[g * 64 + e2];
        #pragma unroll
        for (int f = 0; f < 4; f++)
            v += feat_s[g * 4 + f] * Wfe[(g * 4 + f) * 64 + e2];
        femb_s[o] = v;
    }
    __syncthreads();

    // ilog[g][s]
    #pragma unroll
    for (int i = 0; i < 4; i++) {
        int pr = wid * 4 + i, g = pr >> 2, s = pr & 3;
        float q = 0.f;
        #pragma unroll
        for (int k = 0; k < 16; k++) {
            int d = lane + 32 * k;
            q += hs[d] * Win_h[(g * 512 + d) * 4 + s];
        }
        {
            int e2 = lane;
            q += femb_s[g * 64 + e2] * Win_f[(g * 64 + e2) * 4 + s];
            e2 = lane + 32;
            q += femb_s[g * 64 + e2] * Win_f[(g * 64 + e2) * 4 + s];
        }
        #pragma unroll
        for (int o = 16; o; o >>= 1) q += __shfl_down_sync(0xFFFFFFFFu, q, o);
        if (lane == 0) {
            float c = (float)s * (1.0f / 3.0f);
            float dd = score_s[g] - c;
            ilog_s[pr] = q + bin_b[g * 4 + s] - SHARP_ * dd * dd;  // BIAS=1, TEMP=1
        }
    }
    __syncthreads();

    // gw: top-2 softmax over 8 group logits
    if (tid == 0) {
        float m1 = -FLT_MAX, m2 = -FLT_MAX;
        #pragma unroll
        for (int g = 0; g < 8; g++) {
            float v = glog_s[g];
            if (v > m1) { m2 = m1; m1 = v; } else if (v > m2) m2 = v;
        }
        float ex[8]; float sum = 0.f;
        #pragma unroll
        for (int g = 0; g < 8; g++) {
            float v = glog_s[g];
            if (v >= m2) { ex[g] = expf(v - m1); sum += ex[g]; } else ex[g] = 0.f;
        }
        #pragma unroll
        for (int g = 0; g < 8; g++) gw_s[g] = ex[g] / sum;
    }
    // cw: top-2 softmax over 4 stage logits per group
    if (tid < 8) {
        float m1 = -FLT_MAX, m2 = -FLT_MAX;
        #pragma unroll
        for (int s = 0; s < 4; s++) {
            float v = ilog_s[tid * 4 + s];
            if (v > m1) { m2 = m1; m1 = v; } else if (v > m2) m2 = v;
        }
        float ex[4]; float sum = 0.f;
        #pragma unroll
        for (int s = 0; s < 4; s++) {
            float v = ilog_s[tid * 4 + s];
            if (v >= m2) { ex[s] = expf(v - m1); sum += ex[s]; } else ex[s] = 0.f;
        }
        #pragma unroll
        for (int s = 0; s < 4; s++) cw_s[tid * 4 + s] = ex[s] / sum;
    }
    __syncthreads();
    if (tid < 32) w_s[tid] = gw_s[tid >> 2] * cw_s[tid];
    __syncthreads();

    // y init = w @ be2 (covers every output element)
    #pragma unroll
    for (int d = tid; d < 512; d += 256) {
        float a = 0.f;
        #pragma unroll
        for (int e = 0; e < 32; e++) a += w_s[e] * be2[e * 512 + d];
        y[(size_t)t * 512 + d] = a;
    }

    // scatter active (token, weight) pairs into per-expert lists
    if (tid < 32 && w_s[tid] > 0.f) {
        int pos = atomicAdd(&g_cnt[tid], 1);
        g_tok[tid * NTOK + pos] = t;
        g_wt [tid * NTOK + pos] = w_s[tid];
    }
}

// ---------------- K3: sparse expert FFN (grouped by expert) ----------------
__global__ __launch_bounds__(256) void k_expert(
    const float* __restrict__ H,
    const float* __restrict__ We1, const float* __restrict__ be1,
    const float* __restrict__ We2, float* __restrict__ y)
{
    const int e = blockIdx.x;
    const int n = g_cnt[e];
    const int base = blockIdx.y * 32;
    if (base >= n) return;

    __shared__ __align__(16) float Xs[64][36];
    __shared__ __align__(16) float H1s[256][36];
    __shared__ int   tok_s[32];
    __shared__ float wt_s[32];

    const int tid = threadIdx.x;
    if (tid < 32) {
        int idx = base + tid;
        if (idx < n) { tok_s[tid] = g_tok[e * NTOK + idx]; wt_s[tid] = g_wt[e * NTOK + idx]; }
        else         { tok_s[tid] = g_tok[e * NTOK + base]; wt_s[tid] = 0.f; }
    }
    __syncthreads();

    // phase 1: h1[t][h] = gelu(X @ We1 + be1); thread owns column h=tid
    float acc[32];
    #pragma unroll
    for (int t = 0; t < 32; t++) acc[t] = 0.f;

    const float* W1 = We1 + (size_t)e * 512 * 256;
    for (int kc = 0; kc < 512; kc += 64) {
        #pragma unroll
        for (int it = 0; it < 8; it++) {
            int idx = it * 256 + tid;
            int t = idx >> 6, j = idx & 63;
            Xs[j][t] = H[(size_t)tok_s[t] * 512 + kc + j];
        }
        __syncthreads();
        #pragma unroll 8
        for (int d = 0; d < 64; d++) {
            float wv = W1[(size_t)(kc + d) * 256 + tid];
            const float4* xr = (const float4*)Xs[d];
            #pragma unroll
            for (int q = 0; q < 8; q++) {
                float4 xv = xr[q];
                acc[4*q+0] += xv.x * wv; acc[4*q+1] += xv.y * wv;
                acc[4*q+2] += xv.z * wv; acc[4*q+3] += xv.w * wv;
            }
        }
        __syncthreads();
    }
    {
        float b = be1[e * 256 + tid];
        #pragma unroll
        for (int t = 0; t < 32; t++)
            H1s[tid][t] = gelu_exact(acc[t] + b);
    }
    __syncthreads();

    // phase 2: y[t][d2] += w[t] * (h1[t] @ We2[e][:,d2]); thread owns d2
    const float* W2 = We2 + (size_t)e * 256 * 512;
    #pragma unroll
    for (int half = 0; half < 2; half++) {
        const int d2 = half * 256 + tid;
        float a2[32];
        #pragma unroll
        for (int t = 0; t < 32; t++) a2[t] = 0.f;
        #pragma unroll 8
        for (int h = 0; h < 256; h++) {
            float wv = W2[(size_t)h * 512 + d2];
            const float4* hr = (const float4*)H1s[h];
            #pragma unroll
            for (int q = 0; q < 8; q++) {
                float4 hv = hr[q];
                a2[4*q+0] += hv.x * wv; a2[4*q+1] += hv.y * wv;
                a2[4*q+2] += hv.z * wv; a2[4*q+3] += hv.w * wv;
            }
        }
        #pragma unroll
        for (int t = 0; t < 32; t++) {
            float w = wt_s[t];
            if (w != 0.f)
                atomicAdd(&y[(size_t)tok_s[t] * 512 + d2], w * a2[t]);
        }
    }
}

// ---------------- launch ----------------
extern "C" void kernel_launch(void* const* d_in, const int* in_sizes, int n_in,
                              void* d_out, int out_size) {
    (void)in_sizes; (void)n_in; (void)out_size;
    const float* hidden = (const float*)d_in[0];
    const float* feat   = (const float*)d_in[1];
    // d_in[2] = valid_mask (unused by reference)
    const float* Wr1    = (const float*)d_in[3];
    const float* br1    = (const float*)d_in[4];
    const float* Wr2    = (const float*)d_in[5];
    const float* br2    = (const float*)d_in[6];
    const float* Wfe    = (const float*)d_in[7];
    const float* bfe    = (const float*)d_in[8];
    const float* Win_h  = (const float*)d_in[9];
    const float* Win_f  = (const float*)d_in[10];
    const float* bin_b  = (const float*)d_in[11];
    const float* We1    = (const float*)d_in[12];
    const float* be1    = (const float*)d_in[13];
    const float* We2    = (const float*)d_in[14];
    const float* be2    = (const float*)d_in[15];
    float* y = (float*)d_out;

    k_reset<<<1, 32>>>();
    k_minmax<<<64, 256>>>(feat, NTOK * 32);
    k_gemm1<<<NTOK / 32, 256>>>(hidden, Wr1, br1);
    k_route<<<NTOK, 256>>>(hidden, feat, Wr2, br2, Wfe, bfe,
                           Win_h, Win_f, bin_b, be2, y);
    k_expert<<<dim3(E_, NTOK / 32), 256>>>(hidden, We1, be1, We2, y);
}

// round 2
// speedup vs baseline: 1.7846x; 1.7846x over previous
#include <cuda_runtime.h>
#include <math.h>
#include <float.h>
#include <stdint.h>

#define NTOK 4096
#define DIM  512
#define RH_  256
#define G_   8
#define S_   4
#define E_   32
#define FE_  64
#define DH_  256
#define SHARP_ 16.0f

// ---------------- scratch (device globals; no allocation) ----------------
__device__ float    g_GH[NTOK * RH_];        // gelu(H@Wr1+br1)
__device__ float    g_IL[NTOK * E_];         // hidden @ Win_h (reshaped [512,32])
__device__ int      g_cnt[E_];
__device__ int      g_tok[E_ * NTOK];
__device__ float    g_wt [E_ * NTOK];
__device__ unsigned g_minenc, g_maxenc;

__device__ __forceinline__ unsigned encf(float x) {
    unsigned u = __float_as_uint(x);
    return (u & 0x80000000u) ? ~u : (u | 0x80000000u);
}
__device__ __forceinline__ float decf(unsigned e) {
    return (e & 0x80000000u) ? __uint_as_float(e ^ 0x80000000u)
                             : __uint_as_float(~e);
}
__device__ __forceinline__ float gelu_exact(float x) {
    return 0.5f * x * (1.0f + erff(x * 0.70710678118654752f));
}
__device__ __forceinline__ float cvt_tf32(float x) {
    uint32_t u;
    asm("cvt.rna.tf32.f32 %0, %1;" : "=r"(u) : "f"(x));
    return __uint_as_float(u);
}
__device__ __forceinline__ void mma8(float* c, const uint32_t* a, uint32_t b0, uint32_t b1) {
    asm volatile(
        "mma.sync.aligned.m16n8k8.row.col.f32.tf32.tf32.f32 "
        "{%0,%1,%2,%3},{%4,%5,%6,%7},{%8,%9},{%0,%1,%2,%3};"
        : "+f"(c[0]), "+f"(c[1]), "+f"(c[2]), "+f"(c[3])
        : "r"(a[0]), "r"(a[1]), "r"(a[2]), "r"(a[3]), "r"(b0), "r"(b1));
}

// ---------------- K0a: reset ----------------
__global__ void k_reset() {
    int i = threadIdx.x;
    if (i < E_) g_cnt[i] = 0;
    if (i == 0) { g_minenc = 0xFFFFFFFFu; g_maxenc = 0u; }
}

// ---------------- K0b: feat global min/max ----------------
__global__ void k_minmax(const float* __restrict__ feat, int n) {
    unsigned lmin = 0xFFFFFFFFu, lmax = 0u;
    for (int i = blockIdx.x * blockDim.x + threadIdx.x; i < n; i += gridDim.x * blockDim.x) {
        unsigned e = encf(feat[i]);
        lmin = min(lmin, e); lmax = max(lmax, e);
    }
    #pragma unroll
    for (int o = 16; o; o >>= 1) {
        lmin = min(lmin, __shfl_down_sync(0xFFFFFFFFu, lmin, o));
        lmax = max(lmax, __shfl_down_sync(0xFFFFFFFFu, lmax, o));
    }
    if ((threadIdx.x & 31) == 0) {
        atomicMin(&g_minenc, lmin);
        atomicMax(&g_maxenc, lmax);
    }
}

// ---------------- K1: GH = gelu(H @ Wr1 + br1) ----------------
__global__ __launch_bounds__(256) void k_gemm1(const float* __restrict__ H,
                                               const float* __restrict__ Wr1,
                                               const float* __restrict__ br1) {
    __shared__ __align__(16) float Xs[64][36];
    const int h = threadIdx.x;
    const int base = blockIdx.x * 32;
    float acc[32];
    #pragma unroll
    for (int t = 0; t < 32; t++) acc[t] = 0.f;

    for (int kc = 0; kc < DIM; kc += 64) {
        #pragma unroll
        for (int it = 0; it < 8; it++) {
            int idx = it * 256 + h;
            int t = idx >> 6, j = idx & 63;
            Xs[j][t] = H[(size_t)(base + t) * DIM + kc + j];
        }
        __syncthreads();
        #pragma unroll 8
        for (int d = 0; d < 64; d++) {
            float wv = Wr1[(size_t)(kc + d) * RH_ + h];
            const float4* xr = (const float4*)Xs[d];
            #pragma unroll
            for (int q = 0; q < 8; q++) {
                float4 xv = xr[q];
                acc[4*q+0] += xv.x * wv; acc[4*q+1] += xv.y * wv;
                acc[4*q+2] += xv.z * wv; acc[4*q+3] += xv.w * wv;
            }
        }
        __syncthreads();
    }
    float b = br1[h];
    #pragma unroll
    for (int t = 0; t < 32; t++)
        g_GH[(size_t)(base + t) * RH_ + h] = gelu_exact(acc[t] + b);
}

// ---------------- K1b: IL = hidden @ Win_h reshaped [512,32] ----------------
__global__ __launch_bounds__(256) void k_ilogh(const float* __restrict__ H,
                                               const float* __restrict__ Win_h) {
    __shared__ float Hs[8][512];
    const int tb = blockIdx.x * 8;
    #pragma unroll
    for (int i = 0; i < 16; i++) {
        int idx = i * 256 + threadIdx.x;
        Hs[idx >> 9][idx & 511] = H[(size_t)(tb + (idx >> 9)) * 512 + (idx & 511)];
    }
    __syncthreads();
    const int tl = threadIdx.x >> 5, j = threadIdx.x & 31;
    const int g = j >> 2, s = j & 3;
    const float* W = Win_h + g * 2048 + s;   // Win_h[(g*512+d)*4+s]
    float acc = 0.f;
    #pragma unroll 8
    for (int d = 0; d < 512; d++) acc += Hs[tl][d] * W[d * 4];
    g_IL[(size_t)(tb + tl) * 32 + j] = acc;
}

// ---------------- K2: per-token routing (light) ----------------
__global__ __launch_bounds__(256) void k_route(
    const float* __restrict__ feat,
    const float* __restrict__ Wr2, const float* __restrict__ br2,
    const float* __restrict__ Wfe, const float* __restrict__ bfe,
    const float* __restrict__ Win_f,
    const float* __restrict__ bin_b, const float* __restrict__ be2,
    float* __restrict__ y)
{
    __shared__ float ghs[256], feat_s[32], femb_s[512];
    __shared__ float glog_s[8], ilog_s[32], score_s[8], gw_s[8], cw_s[32], w_s[32];

    const int t = blockIdx.x, tid = threadIdx.x;
    const int wid = tid >> 5, lane = tid & 31;

    ghs[tid] = g_GH[(size_t)t * 256 + tid];
    if (tid < 32) feat_s[tid] = feat[(size_t)t * 32 + tid];
    __syncthreads();

    // glog[g]
    {
        float p = 0.f;
        #pragma unroll
        for (int k = 0; k < 8; k++) {
            int i = lane + 32 * k;
            p += ghs[i] * Wr2[i * 8 + wid];
        }
        #pragma unroll
        for (int o = 16; o; o >>= 1) p += __shfl_down_sync(0xFFFFFFFFu, p, o);
        if (lane == 0) glog_s[wid] = p + br2[wid];
    }

    const bool in01 = (decf(g_minenc) >= -1e-6f) && (decf(g_maxenc) <= 1.0f + 1e-6f);
    if (tid < 8) {
        float sc = 0.f;
        #pragma unroll
        for (int f = 0; f < 4; f++) {
            float x = feat_s[tid * 4 + f];
            float r = in01 ? fminf(fmaxf(x, 0.f), 1.f)
                           : fminf(fmaxf(0.5f * (1.f + erff(x * 0.70710678118654752f)), 0.f), 1.f);
            sc += r;
        }
        score_s[tid] = sc * 0.25f;
    }

    // femb
    #pragma unroll
    for (int o = tid; o < 512; o += 256) {
        int g = o >> 6, e2 = o & 63;
        float v = bfe[g * 64 + e2];
        #pragma unroll
        for (int f = 0; f < 4; f++)
            v += feat_s[g * 4 + f] * Wfe[(g * 4 + f) * 64 + e2];
        femb_s[o] = v;
    }
    __syncthreads();

    // ilog[g][s] = IL (precomputed) + femb part + bias + rule
    #pragma unroll
    for (int i = 0; i < 4; i++) {
        int pr = wid * 4 + i, g = pr >> 2, s = pr & 3;
        float q = 0.f;
        {
            int e2 = lane;
            q += femb_s[g * 64 + e2] * Win_f[(g * 64 + e2) * 4 + s];
            e2 = lane + 32;
            q += femb_s[g * 64 + e2] * Win_f[(g * 64 + e2) * 4 + s];
        }
        #pragma unroll
        for (int o = 16; o; o >>= 1) q += __shfl_down_sync(0xFFFFFFFFu, q, o);
        if (lane == 0) {
            float c = (float)s * (1.0f / 3.0f);
            float dd = score_s[g] - c;
            ilog_s[pr] = q + g_IL[(size_t)t * 32 + pr] + bin_b[pr] - SHARP_ * dd * dd;
        }
    }
    __syncthreads();

    if (tid == 0) {
        float m1 = -FLT_MAX, m2 = -FLT_MAX;
        #pragma unroll
        for (int g = 0; g < 8; g++) {
            float v = glog_s[g];
            if (v > m1) { m2 = m1; m1 = v; } else if (v > m2) m2 = v;
        }
        float ex[8]; float sum = 0.f;
        #pragma unroll
        for (int g = 0; g < 8; g++) {
            float v = glog_s[g];
            if (v >= m2) { ex[g] = expf(v - m1); sum += ex[g]; } else ex[g] = 0.f;
        }
        #pragma unroll
        for (int g = 0; g < 8; g++) gw_s[g] = ex[g] / sum;
    }
    if (tid < 8) {
        float m1 = -FLT_MAX, m2 = -FLT_MAX;
        #pragma unroll
        for (int s = 0; s < 4; s++) {
            float v = ilog_s[tid * 4 + s];
            if (v > m1) { m2 = m1; m1 = v; } else if (v > m2) m2 = v;
        }
        float ex[4]; float sum = 0.f;
        #pragma unroll
        for (int s = 0; s < 4; s++) {
            float v = ilog_s[tid * 4 + s];
            if (v >= m2) { ex[s] = expf(v - m1); sum += ex[s]; } else ex[s] = 0.f;
        }
        #pragma unroll
        for (int s = 0; s < 4; s++) cw_s[tid * 4 + s] = ex[s] / sum;
    }
    __syncthreads();
    if (tid < 32) w_s[tid] = gw_s[tid >> 2] * cw_s[tid];
    __syncthreads();

    #pragma unroll
    for (int d = tid; d < 512; d += 256) {
        float a = 0.f;
        #pragma unroll
        for (int e = 0; e < 32; e++) a += w_s[e] * be2[e * 512 + d];
        y[(size_t)t * 512 + d] = a;
    }

    if (tid < 32 && w_s[tid] > 0.f) {
        int pos = atomicAdd(&g_cnt[tid], 1);
        g_tok[tid * NTOK + pos] = t;
        g_wt [tid * NTOK + pos] = w_s[tid];
    }
}

// ---------------- K3: expert FFN via tf32 mma.sync ----------------
// Block: 64 tokens of one expert. 8 warps = 2 (M) x 4 (N). Warp tile 32x64.
#define XP 40
#define WP 264
#define HP 264
// smem layout offsets (floats)
#define OFF_TOK   0                       // int[64]
#define OFF_WT    64                      // float[64]
#define OFF_BIAS  128                     // float[256]
#define OFF_XS    384                     // float[64*XP]   = 2560
#define OFF_WS    (384 + 64*XP)           // float[32*WP]   = 8448
#define OFF_H1    (384 + 64*XP + 32*WP)   // float[64*HP]   = 16896
#define SMEM_FLOATS (OFF_H1 + 64*HP)
#define SMEM_BYTES  (SMEM_FLOATS * 4)

__global__ __launch_bounds__(256) void k_expert_mma(
    const float* __restrict__ H,
    const float* __restrict__ We1, const float* __restrict__ be1,
    const float* __restrict__ We2, float* __restrict__ y)
{
    extern __shared__ float sm[];
    int*   tok_s  = (int*)sm;
    float* wt_s   = sm + OFF_WT;
    float* bias_s = sm + OFF_BIAS;
    float* Xs     = sm + OFF_XS;
    float* Ws     = sm + OFF_WS;
    float* H1s    = sm + OFF_H1;

    const int e = blockIdx.x;
    const int n = g_cnt[e];
    const int base = blockIdx.y * 64;
    if (base >= n) return;

    const int tid  = threadIdx.x;
    const int w    = tid >> 5;
    const int lane = tid & 31;
    const int gid  = lane >> 2;      // 0..7
    const int tig  = lane & 3;       // 0..3
    const int mwarp = (w & 1) * 32;  // M offset of warp tile
    const int nwarp = (w >> 1) * 64; // N offset of warp tile

    if (tid < 64) {
        int idx = base + tid;
        if (idx < n) { tok_s[tid] = g_tok[e * NTOK + idx]; wt_s[tid] = g_wt[e * NTOK + idx]; }
        else         { tok_s[tid] = g_tok[e * NTOK + base]; wt_s[tid] = 0.f; }
    }
    bias_s[tid] = be1[e * 256 + tid];
    __syncthreads();

    // ---------- phase 1: h1 = gelu(X[64,512] @ We1[512,256] + be1) ----------
    float acc[2][8][4];
    #pragma unroll
    for (int m8 = 0; m8 < 2; m8++)
        #pragma unroll
        for (int n8 = 0; n8 < 8; n8++)
            #pragma unroll
            for (int c = 0; c < 4; c++) acc[m8][n8][c] = 0.f;

    const float* W1 = We1 + (size_t)e * 512 * 256;
    for (int kc = 0; kc < 512; kc += 32) {
        // stage X: 64 tokens x 32 k (cvt tf32)
        #pragma unroll
        for (int i = 0; i < 8; i++) {
            int idx = i * 256 + tid;
            int t = idx >> 5, k = idx & 31;
            Xs[t * XP + k] = cvt_tf32(H[(size_t)tok_s[t] * 512 + kc + k]);
        }
        // stage W1 chunk: 32 rows x 256 cols
        #pragma unroll
        for (int i = 0; i < 8; i++) {
            int idx4 = i * 256 + tid;
            int r = idx4 >> 6, c4 = (idx4 & 63) * 4;
            float4 v = *(const float4*)&W1[(size_t)(kc + r) * 256 + c4];
            float* dst = &Ws[r * WP + c4];
            dst[0] = cvt_tf32(v.x); dst[1] = cvt_tf32(v.y);
            dst[2] = cvt_tf32(v.z); dst[3] = cvt_tf32(v.w);
        }
        __syncthreads();

        #pragma unroll
        for (int ks = 0; ks < 4; ks++) {
            uint32_t a[2][4];
            #pragma unroll
            for (int m8 = 0; m8 < 2; m8++) {
                int r0 = mwarp + m8 * 16 + gid;
                a[m8][0] = __float_as_uint(Xs[r0 * XP + ks * 8 + tig]);
                a[m8][1] = __float_as_uint(Xs[(r0 + 8) * XP + ks * 8 + tig]);
                a[m8][2] = __float_as_uint(Xs[r0 * XP + ks * 8 + tig + 4]);
                a[m8][3] = __float_as_uint(Xs[(r0 + 8) * XP + ks * 8 + tig + 4]);
            }
            #pragma unroll
            for (int n8 = 0; n8 < 8; n8++) {
                int ncol = nwarp + n8 * 8 + gid;
                uint32_t b0 = __float_as_uint(Ws[(ks * 8 + tig) * WP + ncol]);
                uint32_t b1 = __float_as_uint(Ws[(ks * 8 + tig + 4) * WP + ncol]);
                mma8(acc[0][n8], a[0], b0, b1);
                mma8(acc[1][n8], a[1], b0, b1);
            }
        }
        __syncthreads();
    }

    // epilogue 1: bias + gelu -> H1s (tf32)
    #pragma unroll
    for (int m8 = 0; m8 < 2; m8++) {
        #pragma unroll
        for (int n8 = 0; n8 < 8; n8++) {
            #pragma unroll
            for (int c = 0; c < 4; c++) {
                int row = mwarp + m8 * 16 + gid + ((c >= 2) ? 8 : 0);
                int col = nwarp + n8 * 8 + 2 * tig + (c & 1);
                H1s[row * HP + col] = cvt_tf32(gelu_exact(acc[m8][n8][c] + bias_s[col]));
            }
        }
    }
    __syncthreads();

    // ---------- phase 2: y += w * (h1[64,256] @ We2[256,512]) ----------
    const float* W2 = We2 + (size_t)e * 256 * 512;
    #pragma unroll
    for (int half = 0; half < 2; half++) {
        #pragma unroll
        for (int m8 = 0; m8 < 2; m8++)
            #pragma unroll
            for (int n8 = 0; n8 < 8; n8++)
                #pragma unroll
                for (int c = 0; c < 4; c++) acc[m8][n8][c] = 0.f;

        for (int kc = 0; kc < 256; kc += 32) {
            #pragma unroll
            for (int i = 0; i < 8; i++) {
                int idx4 = i * 256 + tid;
                int r = idx4 >> 6, c4 = (idx4 & 63) * 4;
                float4 v = *(const float4*)&W2[(size_t)(kc + r) * 512 + half * 256 + c4];
                float* dst = &Ws[r * WP + c4];
                dst[0] = cvt_tf32(v.x); dst[1] = cvt_tf32(v.y);
                dst[2] = cvt_tf32(v.z); dst[3] = cvt_tf32(v.w);
            }
            __syncthreads();

            #pragma unroll
            for (int ks = 0; ks < 4; ks++) {
                uint32_t a[2][4];
                #pragma unroll
                for (int m8 = 0; m8 < 2; m8++) {
                    int r0 = mwarp + m8 * 16 + gid;
                    int k0 = kc + ks * 8 + tig;
                    a[m8][0] = __float_as_uint(H1s[r0 * HP + k0]);
                    a[m8][1] = __float_as_uint(H1s[(r0 + 8) * HP + k0]);
                    a[m8][2] = __float_as_uint(H1s[r0 * HP + k0 + 4]);
                    a[m8][3] = __float_as_uint(H1s[(r0 + 8) * HP + k0 + 4]);
                }
                #pragma unroll
                for (int n8 = 0; n8 < 8; n8++) {
                    int ncol = nwarp + n8 * 8 + gid;
                    uint32_t b0 = __float_as_uint(Ws[(ks * 8 + tig) * WP + ncol]);
                    uint32_t b1 = __float_as_uint(Ws[(ks * 8 + tig + 4) * WP + ncol]);
                    mma8(acc[0][n8], a[0], b0, b1);
                    mma8(acc[1][n8], a[1], b0, b1);
                }
            }
            __syncthreads();
        }

        // epilogue 2: scaled atomic accumulate into y
        #pragma unroll
        for (int m8 = 0; m8 < 2; m8++) {
            #pragma unroll
            for (int c2 = 0; c2 < 2; c2++) {          // c pairs by row
                int row = mwarp + m8 * 16 + gid + (c2 ? 8 : 0);
                float wgt = wt_s[row];
                if (wgt == 0.f) continue;
                int tok = tok_s[row];
                #pragma unroll
                for (int n8 = 0; n8 < 8; n8++) {
                    int col = half * 256 + nwarp + n8 * 8 + 2 * tig;
                    atomicAdd(&y[(size_t)tok * 512 + col],     wgt * acc[m8][n8][c2 * 2 + 0]);
                    atomicAdd(&y[(size_t)tok * 512 + col + 1], wgt * acc[m8][n8][c2 * 2 + 1]);
                }
            }
        }
    }
}

// ---------------- launch ----------------
extern "C" void kernel_launch(void* const* d_in, const int* in_sizes, int n_in,
                              void* d_out, int out_size) {
    (void)in_sizes; (void)n_in; (void)out_size;
    const float* hidden = (const float*)d_in[0];
    const float* feat   = (const float*)d_in[1];
    const float* Wr1    = (const float*)d_in[3];
    const float* br1    = (const float*)d_in[4];
    const float* Wr2    = (const float*)d_in[5];
    const float* br2    = (const float*)d_in[6];
    const float* Wfe    = (const float*)d_in[7];
    const float* bfe    = (const float*)d_in[8];
    const float* Win_h  = (const float*)d_in[9];
    const float* Win_f  = (const float*)d_in[10];
    const float* bin_b  = (const float*)d_in[11];
    const float* We1    = (const float*)d_in[12];
    const float* be1    = (const float*)d_in[13];
    const float* We2    = (const float*)d_in[14];
    const float* be2    = (const float*)d_in[15];
    float* y = (float*)d_out;

    static bool attr_set = false;
    if (!attr_set) {
        cudaFuncSetAttribute(k_expert_mma, cudaFuncAttributeMaxDynamicSharedMemorySize, SMEM_BYTES);
        attr_set = true;
    }

    k_reset<<<1, 32>>>();
    k_minmax<<<64, 256>>>(feat, NTOK * 32);
    k_gemm1<<<NTOK / 32, 256>>>(hidden, Wr1, br1);
    k_ilogh<<<NTOK / 8, 256>>>(hidden, Win_h);
    k_route<<<NTOK, 256>>>(feat, Wr2, br2, Wfe, bfe,
                           Win_f, bin_b, be2, y);
    k_expert_mma<<<dim3(E_, NTOK / 64), 256, SMEM_BYTES>>>(hidden, We1, be1, We2, y);
}

// round 3
// speedup vs baseline: 2.0198x; 1.1318x over previous
#include <cuda_runtime.h>
#include <math.h>
#include <float.h>
#include <stdint.h>

#define NTOK 4096
#define DIM  512
#define RH_  256
#define G_   8
#define S_   4
#define E_   32
#define FE_  64
#define DH_  256
#define SHARP_ 16.0f

// ---------------- scratch ----------------
__device__ float    g_GH[NTOK * RH_];
__device__ float    g_IL[NTOK * E_];
__device__ int      g_cnt[E_];
__device__ int      g_tok[E_ * NTOK];
__device__ float    g_wt [E_ * NTOK];
__device__ unsigned g_minenc, g_maxenc;

__device__ __forceinline__ unsigned encf(float x) {
    unsigned u = __float_as_uint(x);
    return (u & 0x80000000u) ? ~u : (u | 0x80000000u);
}
__device__ __forceinline__ float decf(unsigned e) {
    return (e & 0x80000000u) ? __uint_as_float(e ^ 0x80000000u)
                             : __uint_as_float(~e);
}
__device__ __forceinline__ float gelu_exact(float x) {
    return 0.5f * x * (1.0f + erff(x * 0.70710678118654752f));
}
__device__ __forceinline__ float cvt_tf32(float x) {
    uint32_t u;
    asm("cvt.rna.tf32.f32 %0, %1;" : "=r"(u) : "f"(x));
    return __uint_as_float(u);
}
__device__ __forceinline__ void mma8(float* c, const uint32_t* a, uint32_t b0, uint32_t b1) {
    asm volatile(
        "mma.sync.aligned.m16n8k8.row.col.f32.tf32.tf32.f32 "
        "{%0,%1,%2,%3},{%4,%5,%6,%7},{%8,%9},{%0,%1,%2,%3};"
        : "+f"(c[0]), "+f"(c[1]), "+f"(c[2]), "+f"(c[3])
        : "r"(a[0]), "r"(a[1]), "r"(a[2]), "r"(a[3]), "r"(b0), "r"(b1));
}

// ---------------- K0a: reset ----------------
__global__ void k_reset() {
    int i = threadIdx.x;
    if (i < E_) g_cnt[i] = 0;
    if (i == 0) { g_minenc = 0xFFFFFFFFu; g_maxenc = 0u; }
}

// ---------------- K0b: feat global min/max ----------------
__global__ void k_minmax(const float* __restrict__ feat, int n) {
    unsigned lmin = 0xFFFFFFFFu, lmax = 0u;
    for (int i = blockIdx.x * blockDim.x + threadIdx.x; i < n; i += gridDim.x * blockDim.x) {
        unsigned e = encf(feat[i]);
        lmin = min(lmin, e); lmax = max(lmax, e);
    }
    #pragma unroll
    for (int o = 16; o; o >>= 1) {
        lmin = min(lmin, __shfl_down_sync(0xFFFFFFFFu, lmin, o));
        lmax = max(lmax, __shfl_down_sync(0xFFFFFFFFu, lmax, o));
    }
    if ((threadIdx.x & 31) == 0) {
        atomicMin(&g_minenc, lmin);
        atomicMax(&g_maxenc, lmax);
    }
}

// ---------------- K1: GH = gelu(H @ Wr1 + br1)  +  IL = H @ Win_h ----------------
__global__ __launch_bounds__(256) void k_gemm1(const float* __restrict__ H,
                                               const float* __restrict__ Wr1,
                                               const float* __restrict__ br1,
                                               const float* __restrict__ Win_h) {
    __shared__ __align__(16) float Xs[64][36];
    const int h = threadIdx.x;
    const int base = blockIdx.x * 32;
    // IL assignment: token tI = tid>>3 (32 tokens), cols (tid&7)*4 .. +3
    const int tI = h >> 3;
    const int gI = h & 7;                 // group index == column group
    float acc[32];
    float4 acc2 = make_float4(0.f, 0.f, 0.f, 0.f);
    #pragma unroll
    for (int t = 0; t < 32; t++) acc[t] = 0.f;

    for (int kc = 0; kc < DIM; kc += 64) {
        #pragma unroll
        for (int it = 0; it < 8; it++) {
            int idx = it * 256 + h;
            int t = idx >> 6, j = idx & 63;
            Xs[j][t] = H[(size_t)(base + t) * DIM + kc + j];
        }
        __syncthreads();
        #pragma unroll 8
        for (int d = 0; d < 64; d++) {
            float wv = Wr1[(size_t)(kc + d) * RH_ + h];
            const float4* xr = (const float4*)Xs[d];
            #pragma unroll
            for (int q = 0; q < 8; q++) {
                float4 xv = xr[q];
                acc[4*q+0] += xv.x * wv; acc[4*q+1] += xv.y * wv;
                acc[4*q+2] += xv.z * wv; acc[4*q+3] += xv.w * wv;
            }
        }
        // IL accumulation on the same staged tile
        #pragma unroll 4
        for (int d = 0; d < 64; d++) {
            float xv = Xs[d][tI];
            float4 wv = *(const float4*)&Win_h[gI * 2048 + (kc + d) * 4];
            acc2.x += xv * wv.x; acc2.y += xv * wv.y;
            acc2.z += xv * wv.z; acc2.w += xv * wv.w;
        }
        __syncthreads();
    }
    float b = br1[h];
    #pragma unroll
    for (int t = 0; t < 32; t++)
        g_GH[(size_t)(base + t) * RH_ + h] = gelu_exact(acc[t] + b);
    *(float4*)&g_IL[(size_t)(base + tI) * 32 + gI * 4] = acc2;
}

// ---------------- K2: per-token routing ----------------
__global__ __launch_bounds__(256) void k_route(
    const float* __restrict__ feat,
    const float* __restrict__ Wr2, const float* __restrict__ br2,
    const float* __restrict__ Wfe, const float* __restrict__ bfe,
    const float* __restrict__ Win_f,
    const float* __restrict__ bin_b, const float* __restrict__ be2,
    float* __restrict__ y)
{
    __shared__ float ghs[256], feat_s[32], femb_s[512];
    __shared__ float glog_s[8], ilog_s[32], score_s[8], gw_s[8], cw_s[32], w_s[32];

    const int t = blockIdx.x, tid = threadIdx.x;
    const int wid = tid >> 5, lane = tid & 31;

    ghs[tid] = g_GH[(size_t)t * 256 + tid];
    if (tid < 32) feat_s[tid] = feat[(size_t)t * 32 + tid];
    __syncthreads();

    {
        float p = 0.f;
        #pragma unroll
        for (int k = 0; k < 8; k++) {
            int i = lane + 32 * k;
            p += ghs[i] * Wr2[i * 8 + wid];
        }
        #pragma unroll
        for (int o = 16; o; o >>= 1) p += __shfl_down_sync(0xFFFFFFFFu, p, o);
        if (lane == 0) glog_s[wid] = p + br2[wid];
    }

    const bool in01 = (decf(g_minenc) >= -1e-6f) && (decf(g_maxenc) <= 1.0f + 1e-6f);
    if (tid < 8) {
        float sc = 0.f;
        #pragma unroll
        for (int f = 0; f < 4; f++) {
            float x = feat_s[tid * 4 + f];
            float r = in01 ? fminf(fmaxf(x, 0.f), 1.f)
                           : fminf(fmaxf(0.5f * (1.f + erff(x * 0.70710678118654752f)), 0.f), 1.f);
            sc += r;
        }
        score_s[tid] = sc * 0.25f;
    }

    #pragma unroll
    for (int o = tid; o < 512; o += 256) {
        int g = o >> 6, e2 = o & 63;
        float v = bfe[g * 64 + e2];
        #pragma unroll
        for (int f = 0; f < 4; f++)
            v += feat_s[g * 4 + f] * Wfe[(g * 4 + f) * 64 + e2];
        femb_s[o] = v;
    }
    __syncthreads();

    #pragma unroll
    for (int i = 0; i < 4; i++) {
        int pr = wid * 4 + i, g = pr >> 2, s = pr & 3;
        float q = 0.f;
        {
            int e2 = lane;
            q += femb_s[g * 64 + e2] * Win_f[(g * 64 + e2) * 4 + s];
            e2 = lane + 32;
            q += femb_s[g * 64 + e2] * Win_f[(g * 64 + e2) * 4 + s];
        }
        #pragma unroll
        for (int o = 16; o; o >>= 1) q += __shfl_down_sync(0xFFFFFFFFu, q, o);
        if (lane == 0) {
            float c = (float)s * (1.0f / 3.0f);
            float dd = score_s[g] - c;
            ilog_s[pr] = q + g_IL[(size_t)t * 32 + pr] + bin_b[pr] - SHARP_ * dd * dd;
        }
    }
    __syncthreads();

    if (tid == 0) {
        float m1 = -FLT_MAX, m2 = -FLT_MAX;
        #pragma unroll
        for (int g = 0; g < 8; g++) {
            float v = glog_s[g];
            if (v > m1) { m2 = m1; m1 = v; } else if (v > m2) m2 = v;
        }
        float ex[8]; float sum = 0.f;
        #pragma unroll
        for (int g = 0; g < 8; g++) {
            float v = glog_s[g];
            if (v >= m2) { ex[g] = expf(v - m1); sum += ex[g]; } else ex[g] = 0.f;
        }
        #pragma unroll
        for (int g = 0; g < 8; g++) gw_s[g] = ex[g] / sum;
    }
    if (tid < 8) {
        float m1 = -FLT_MAX, m2 = -FLT_MAX;
        #pragma unroll
        for (int s = 0; s < 4; s++) {
            float v = ilog_s[tid * 4 + s];
            if (v > m1) { m2 = m1; m1 = v; } else if (v > m2) m2 = v;
        }
        float ex[4]; float sum = 0.f;
        #pragma unroll
        for (int s = 0; s < 4; s++) {
            float v = ilog_s[tid * 4 + s];
            if (v >= m2) { ex[s] = expf(v - m1); sum += ex[s]; } else ex[s] = 0.f;
        }
        #pragma unroll
        for (int s = 0; s < 4; s++) cw_s[tid * 4 + s] = ex[s] / sum;
    }
    __syncthreads();
    if (tid < 32) w_s[tid] = gw_s[tid >> 2] * cw_s[tid];
    __syncthreads();

    #pragma unroll
    for (int d = tid; d < 512; d += 256) {
        float a = 0.f;
        #pragma unroll
        for (int e = 0; e < 32; e++) a += w_s[e] * be2[e * 512 + d];
        y[(size_t)t * 512 + d] = a;
    }

    if (tid < 32 && w_s[tid] > 0.f) {
        int pos = atomicAdd(&g_cnt[tid], 1);
        g_tok[tid * NTOK + pos] = t;
        g_wt [tid * NTOK + pos] = w_s[tid];
    }
}

// ---------------- K3: expert FFN via tf32 mma.sync, software pipelined ----------------
#define XP 40
#define WP 264
#define HP 264
#define OFF_TOK   0
#define OFF_WT    64
#define OFF_BIAS  128
#define OFF_XS    384
#define OFF_WS    (384 + 64*XP)
#define OFF_H1    (384 + 64*XP + 32*WP)
#define SMEM_FLOATS (OFF_H1 + 64*HP)
#define SMEM_BYTES  (SMEM_FLOATS * 4)

__global__ __launch_bounds__(256) void k_expert_mma(
    const float* __restrict__ H,
    const float* __restrict__ We1, const float* __restrict__ be1,
    const float* __restrict__ We2, float* __restrict__ y)
{
    extern __shared__ float sm[];
    int*   tok_s  = (int*)sm;
    float* wt_s   = sm + OFF_WT;
    float* bias_s = sm + OFF_BIAS;
    float* Xs     = sm + OFF_XS;
    float* Ws     = sm + OFF_WS;
    float* H1s    = sm + OFF_H1;

    const int e = blockIdx.x;
    const int n = g_cnt[e];
    const int base = blockIdx.y * 64;
    if (base >= n) return;

    const int tid  = threadIdx.x;
    const int w    = tid >> 5;
    const int lane = tid & 31;
    const int gid  = lane >> 2;
    const int tig  = lane & 3;
    const int mwarp = (w & 1) * 32;
    const int nwarp = (w >> 1) * 64;

    if (tid < 64) {
        int idx = base + tid;
        if (idx < n) { tok_s[tid] = g_tok[e * NTOK + idx]; wt_s[tid] = g_wt[e * NTOK + idx]; }
        else         { tok_s[tid] = g_tok[e * NTOK + base]; wt_s[tid] = 0.f; }
    }
    bias_s[tid] = be1[e * 256 + tid];
    __syncthreads();

    // thread's staging coordinates
    const int xt = tid >> 5, xk = tid & 31;          // X: 8 rows of (t,k) pairs strided
    const int wr = tid >> 6, wc4 = (tid & 63) * 4;   // W: rows strided by 4

    float acc[2][8][4];
    float4 wbuf[8];
    float  xbuf[8];

    // ---------- phase 1 ----------
    #pragma unroll
    for (int m8 = 0; m8 < 2; m8++)
        #pragma unroll
        for (int n8 = 0; n8 < 8; n8++)
            #pragma unroll
            for (int c = 0; c < 4; c++) acc[m8][n8][c] = 0.f;

    const float* W1 = We1 + (size_t)e * 512 * 256;

    // prefetch chunk 0
    #pragma unroll
    for (int i = 0; i < 8; i++) {
        int t = (i * 256 + tid) >> 5;
        xbuf[i] = H[(size_t)tok_s[t] * 512 + xk];
        wbuf[i] = *(const float4*)&W1[(size_t)(i * 4 + wr) * 256 + wc4];
    }

    for (int kc = 0; kc < 512; kc += 32) {
        // store prefetched chunk to smem (cvt)
        #pragma unroll
        for (int i = 0; i < 8; i++) {
            int t = (i * 256 + tid) >> 5;
            Xs[t * XP + xk] = cvt_tf32(xbuf[i]);
            float* dst = &Ws[(i * 4 + wr) * WP + wc4];
            dst[0] = cvt_tf32(wbuf[i].x); dst[1] = cvt_tf32(wbuf[i].y);
            dst[2] = cvt_tf32(wbuf[i].z); dst[3] = cvt_tf32(wbuf[i].w);
        }
        __syncthreads();

        // prefetch next chunk (overlaps with MMA below)
        if (kc + 32 < 512) {
            #pragma unroll
            for (int i = 0; i < 8; i++) {
                int t = (i * 256 + tid) >> 5;
                xbuf[i] = H[(size_t)tok_s[t] * 512 + kc + 32 + xk];
                wbuf[i] = *(const float4*)&W1[(size_t)(kc + 32 + i * 4 + wr) * 256 + wc4];
            }
        }

        #pragma unroll
        for (int ks = 0; ks < 4; ks++) {
            uint32_t a[2][4];
            #pragma unroll
            for (int m8 = 0; m8 < 2; m8++) {
                int r0 = mwarp + m8 * 16 + gid;
                a[m8][0] = __float_as_uint(Xs[r0 * XP + ks * 8 + tig]);
                a[m8][1] = __float_as_uint(Xs[(r0 + 8) * XP + ks * 8 + tig]);
                a[m8][2] = __float_as_uint(Xs[r0 * XP + ks * 8 + tig + 4]);
                a[m8][3] = __float_as_uint(Xs[(r0 + 8) * XP + ks * 8 + tig + 4]);
            }
            #pragma unroll
            for (int n8 = 0; n8 < 8; n8++) {
                int ncol = nwarp + n8 * 8 + gid;
                uint32_t b0 = __float_as_uint(Ws[(ks * 8 + tig) * WP + ncol]);
                uint32_t b1 = __float_as_uint(Ws[(ks * 8 + tig + 4) * WP + ncol]);
                mma8(acc[0][n8], a[0], b0, b1);
                mma8(acc[1][n8], a[1], b0, b1);
            }
        }
        __syncthreads();
    }

    // epilogue 1: bias + gelu -> H1s
    #pragma unroll
    for (int m8 = 0; m8 < 2; m8++) {
        #pragma unroll
        for (int n8 = 0; n8 < 8; n8++) {
            #pragma unroll
            for (int c = 0; c < 4; c++) {
                int row = mwarp + m8 * 16 + gid + ((c >= 2) ? 8 : 0);
                int col = nwarp + n8 * 8 + 2 * tig + (c & 1);
                H1s[row * HP + col] = cvt_tf32(gelu_exact(acc[m8][n8][c] + bias_s[col]));
            }
        }
    }
    __syncthreads();

    // ---------- phase 2 ----------
    const float* W2 = We2 + (size_t)e * 256 * 512;
    #pragma unroll
    for (int half = 0; half < 2; half++) {
        #pragma unroll
        for (int m8 = 0; m8 < 2; m8++)
            #pragma unroll
            for (int n8 = 0; n8 < 8; n8++)
                #pragma unroll
                for (int c = 0; c < 4; c++) acc[m8][n8][c] = 0.f;

        // prefetch chunk 0
        #pragma unroll
        for (int i = 0; i < 8; i++)
            wbuf[i] = *(const float4*)&W2[(size_t)(i * 4 + wr) * 512 + half * 256 + wc4];

        for (int kc = 0; kc < 256; kc += 32) {
            #pragma unroll
            for (int i = 0; i < 8; i++) {
                float* dst = &Ws[(i * 4 + wr) * WP + wc4];
                dst[0] = cvt_tf32(wbuf[i].x); dst[1] = cvt_tf32(wbuf[i].y);
                dst[2] = cvt_tf32(wbuf[i].z); dst[3] = cvt_tf32(wbuf[i].w);
            }
            __syncthreads();

            if (kc + 32 < 256) {
                #pragma unroll
                for (int i = 0; i < 8; i++)
                    wbuf[i] = *(const float4*)&W2[(size_t)(kc + 32 + i * 4 + wr) * 512 + half * 256 + wc4];
            }

            #pragma unroll
            for (int ks = 0; ks < 4; ks++) {
                uint32_t a[2][4];
                #pragma unroll
                for (int m8 = 0; m8 < 2; m8++) {
                    int r0 = mwarp + m8 * 16 + gid;
                    int k0 = kc + ks * 8 + tig;
                    a[m8][0] = __float_as_uint(H1s[r0 * HP + k0]);
                    a[m8][1] = __float_as_uint(H1s[(r0 + 8) * HP + k0]);
                    a[m8][2] = __float_as_uint(H1s[r0 * HP + k0 + 4]);
                    a[m8][3] = __float_as_uint(H1s[(r0 + 8) * HP + k0 + 4]);
                }
                #pragma unroll
                for (int n8 = 0; n8 < 8; n8++) {
                    int ncol = nwarp + n8 * 8 + gid;
                    uint32_t b0 = __float_as_uint(Ws[(ks * 8 + tig) * WP + ncol]);
                    uint32_t b1 = __float_as_uint(Ws[(ks * 8 + tig + 4) * WP + ncol]);
                    mma8(acc[0][n8], a[0], b0, b1);
                    mma8(acc[1][n8], a[1], b0, b1);
                }
            }
            __syncthreads();
        }

        #pragma unroll
        for (int m8 = 0; m8 < 2; m8++) {
            #pragma unroll
            for (int c2 = 0; c2 < 2; c2++) {
                int row = mwarp + m8 * 16 + gid + (c2 ? 8 : 0);
                float wgt = wt_s[row];
                if (wgt == 0.f) continue;
                int tok = tok_s[row];
                #pragma unroll
                for (int n8 = 0; n8 < 8; n8++) {
                    int col = half * 256 + nwarp + n8 * 8 + 2 * tig;
                    atomicAdd(&y[(size_t)tok * 512 + col],     wgt * acc[m8][n8][c2 * 2 + 0]);
                    atomicAdd(&y[(size_t)tok * 512 + col + 1], wgt * acc[m8][n8][c2 * 2 + 1]);
                }
            }
        }
    }
}

// ---------------- launch ----------------
extern "C" void kernel_launch(void* const* d_in, const int* in_sizes, int n_in,
                              void* d_out, int out_size) {
    (void)in_sizes; (void)n_in; (void)out_size;
    const float* hidden = (const float*)d_in[0];
    const float* feat   = (const float*)d_in[1];
    const float* Wr1    = (const float*)d_in[3];
    const float* br1    = (const float*)d_in[4];
    const float* Wr2    = (const float*)d_in[5];
    const float* br2    = (const float*)d_in[6];
    const float* Wfe    = (const float*)d_in[7];
    const float* bfe    = (const float*)d_in[8];
    const float* Win_h  = (const float*)d_in[9];
    const float* Win_f  = (const float*)d_in[10];
    const float* bin_b  = (const float*)d_in[11];
    const float* We1    = (const float*)d_in[12];
    const float* be1    = (const float*)d_in[13];
    const float* We2    = (const float*)d_in[14];
    const float* be2    = (const float*)d_in[15];
    float* y = (float*)d_out;

    static bool attr_set = false;
    if (!attr_set) {
        cudaFuncSetAttribute(k_expert_mma, cudaFuncAttributeMaxDynamicSharedMemorySize, SMEM_BYTES);
        attr_set = true;
    }

    k_reset<<<1, 32>>>();
    k_minmax<<<64, 256>>>(feat, NTOK * 32);
    k_gemm1<<<NTOK / 32, 256>>>(hidden, Wr1, br1, Win_h);
    k_route<<<NTOK, 256>>>(feat, Wr2, br2, Wfe, bfe,
                           Win_f, bin_b, be2, y);
    k_expert_mma<<<dim3(E_, NTOK / 64), 256, SMEM_BYTES>>>(hidden, We1, be1, We2, y);
}

// round 4
// speedup vs baseline: 2.3388x; 1.1580x over previous
#include <cuda_runtime.h>
#include <cuda_fp16.h>
#include <math.h>
#include <float.h>
#include <stdint.h>

#define NTOK 4096
#define DIM  512
#define RH_  256
#define E_   32
#define SHARP_ 16.0f

// ---------------- scratch ----------------
__device__ float    g_GH[NTOK * RH_];
__device__ float    g_IL[NTOK * E_];
__device__ int      g_cnt[E_];
__device__ int      g_tok[E_ * NTOK];
__device__ float    g_wt [E_ * NTOK];
__device__ unsigned g_minenc, g_maxenc;

__device__ __forceinline__ unsigned encf(float x) {
    unsigned u = __float_as_uint(x);
    return (u & 0x80000000u) ? ~u : (u | 0x80000000u);
}
__device__ __forceinline__ float decf(unsigned e) {
    return (e & 0x80000000u) ? __uint_as_float(e ^ 0x80000000u)
                             : __uint_as_float(~e);
}
__device__ __forceinline__ float gelu_exact(float x) {
    return 0.5f * x * (1.0f + erff(x * 0.70710678118654752f));
}
__device__ __forceinline__ uint32_t pack_h2(float a, float b) {
    __half2 h = __floats2half2_rn(a, b);
    return *(uint32_t*)&h;
}
__device__ __forceinline__ void mma16(float* c, const uint32_t* a, uint32_t b0, uint32_t b1) {
    asm volatile(
        "mma.sync.aligned.m16n8k16.row.col.f32.f16.f16.f32 "
        "{%0,%1,%2,%3},{%4,%5,%6,%7},{%8,%9},{%0,%1,%2,%3};"
        : "+f"(c[0]), "+f"(c[1]), "+f"(c[2]), "+f"(c[3])
        : "r"(a[0]), "r"(a[1]), "r"(a[2]), "r"(a[3]), "r"(b0), "r"(b1));
}

// ---------------- K0a: reset ----------------
__global__ void k_reset() {
    int i = threadIdx.x;
    if (i < E_) g_cnt[i] = 0;
    if (i == 0) { g_minenc = 0xFFFFFFFFu; g_maxenc = 0u; }
}

// ---------------- K0b: feat global min/max ----------------
__global__ void k_minmax(const float* __restrict__ feat, int n) {
    unsigned lmin = 0xFFFFFFFFu, lmax = 0u;
    for (int i = blockIdx.x * blockDim.x + threadIdx.x; i < n; i += gridDim.x * blockDim.x) {
        unsigned e = encf(feat[i]);
        lmin = min(lmin, e); lmax = max(lmax, e);
    }
    #pragma unroll
    for (int o = 16; o; o >>= 1) {
        lmin = min(lmin, __shfl_down_sync(0xFFFFFFFFu, lmin, o));
        lmax = max(lmax, __shfl_down_sync(0xFFFFFFFFu, lmax, o));
    }
    if ((threadIdx.x & 31) == 0) {
        atomicMin(&g_minenc, lmin);
        atomicMax(&g_maxenc, lmax);
    }
}

// ---------------- K1: GH = gelu(H @ Wr1 + br1)  +  IL = H @ Win_h (fp32, routing-exact) ----------------
__global__ __launch_bounds__(256) void k_gemm1(const float* __restrict__ H,
                                               const float* __restrict__ Wr1,
                                               const float* __restrict__ br1,
                                               const float* __restrict__ Win_h) {
    __shared__ __align__(16) float Xs[64][36];
    const int h = threadIdx.x;
    const int base = blockIdx.x * 32;
    const int tI = h >> 3;
    const int gI = h & 7;
    float acc[32];
    float4 acc2 = make_float4(0.f, 0.f, 0.f, 0.f);
    #pragma unroll
    for (int t = 0; t < 32; t++) acc[t] = 0.f;

    for (int kc = 0; kc < DIM; kc += 64) {
        #pragma unroll
        for (int it = 0; it < 8; it++) {
            int idx = it * 256 + h;
            int t = idx >> 6, j = idx & 63;
            Xs[j][t] = H[(size_t)(base + t) * DIM + kc + j];
        }
        __syncthreads();
        #pragma unroll 8
        for (int d = 0; d < 64; d++) {
            float wv = Wr1[(size_t)(kc + d) * RH_ + h];
            const float4* xr = (const float4*)Xs[d];
            #pragma unroll
            for (int q = 0; q < 8; q++) {
                float4 xv = xr[q];
                acc[4*q+0] += xv.x * wv; acc[4*q+1] += xv.y * wv;
                acc[4*q+2] += xv.z * wv; acc[4*q+3] += xv.w * wv;
            }
        }
        #pragma unroll 4
        for (int d = 0; d < 64; d++) {
            float xv = Xs[d][tI];
            float4 wv = *(const float4*)&Win_h[gI * 2048 + (kc + d) * 4];
            acc2.x += xv * wv.x; acc2.y += xv * wv.y;
            acc2.z += xv * wv.z; acc2.w += xv * wv.w;
        }
        __syncthreads();
    }
    float b = br1[h];
    #pragma unroll
    for (int t = 0; t < 32; t++)
        g_GH[(size_t)(base + t) * RH_ + h] = gelu_exact(acc[t] + b);
    *(float4*)&g_IL[(size_t)(base + tI) * 32 + gI * 4] = acc2;
}

// ---------------- K2: per-token routing (fp32 exact) ----------------
__global__ __launch_bounds__(256) void k_route(
    const float* __restrict__ feat,
    const float* __restrict__ Wr2, const float* __restrict__ br2,
    const float* __restrict__ Wfe, const float* __restrict__ bfe,
    const float* __restrict__ Win_f,
    const float* __restrict__ bin_b, const float* __restrict__ be2,
    float* __restrict__ y)
{
    __shared__ float ghs[256], feat_s[32], femb_s[512];
    __shared__ float glog_s[8], ilog_s[32], score_s[8], gw_s[8], cw_s[32], w_s[32];

    const int t = blockIdx.x, tid = threadIdx.x;
    const int wid = tid >> 5, lane = tid & 31;

    ghs[tid] = g_GH[(size_t)t * 256 + tid];
    if (tid < 32) feat_s[tid] = feat[(size_t)t * 32 + tid];
    __syncthreads();

    {
        float p = 0.f;
        #pragma unroll
        for (int k = 0; k < 8; k++) {
            int i = lane + 32 * k;
            p += ghs[i] * Wr2[i * 8 + wid];
        }
        #pragma unroll
        for (int o = 16; o; o >>= 1) p += __shfl_down_sync(0xFFFFFFFFu, p, o);
        if (lane == 0) glog_s[wid] = p + br2[wid];
    }

    const bool in01 = (decf(g_minenc) >= -1e-6f) && (decf(g_maxenc) <= 1.0f + 1e-6f);
    if (tid < 8) {
        float sc = 0.f;
        #pragma unroll
        for (int f = 0; f < 4; f++) {
            float x = feat_s[tid * 4 + f];
            float r = in01 ? fminf(fmaxf(x, 0.f), 1.f)
                           : fminf(fmaxf(0.5f * (1.f + erff(x * 0.70710678118654752f)), 0.f), 1.f);
            sc += r;
        }
        score_s[tid] = sc * 0.25f;
    }

    #pragma unroll
    for (int o = tid; o < 512; o += 256) {
        int g = o >> 6, e2 = o & 63;
        float v = bfe[g * 64 + e2];
        #pragma unroll
        for (int f = 0; f < 4; f++)
            v += feat_s[g * 4 + f] * Wfe[(g * 4 + f) * 64 + e2];
        femb_s[o] = v;
    }
    __syncthreads();

    #pragma unroll
    for (int i = 0; i < 4; i++) {
        int pr = wid * 4 + i, g = pr >> 2, s = pr & 3;
        float q = 0.f;
        {
            int e2 = lane;
            q += femb_s[g * 64 + e2] * Win_f[(g * 64 + e2) * 4 + s];
            e2 = lane + 32;
            q += femb_s[g * 64 + e2] * Win_f[(g * 64 + e2) * 4 + s];
        }
        #pragma unroll
        for (int o = 16; o; o >>= 1) q += __shfl_down_sync(0xFFFFFFFFu, q, o);
        if (lane == 0) {
            float c = (float)s * (1.0f / 3.0f);
            float dd = score_s[g] - c;
            ilog_s[pr] = q + g_IL[(size_t)t * 32 + pr] + bin_b[pr] - SHARP_ * dd * dd;
        }
    }
    __syncthreads();

    if (tid == 0) {
        float m1 = -FLT_MAX, m2 = -FLT_MAX;
        #pragma unroll
        for (int g = 0; g < 8; g++) {
            float v = glog_s[g];
            if (v > m1) { m2 = m1; m1 = v; } else if (v > m2) m2 = v;
        }
        float ex[8]; float sum = 0.f;
        #pragma unroll
        for (int g = 0; g < 8; g++) {
            float v = glog_s[g];
            if (v >= m2) { ex[g] = expf(v - m1); sum += ex[g]; } else ex[g] = 0.f;
        }
        #pragma unroll
        for (int g = 0; g < 8; g++) gw_s[g] = ex[g] / sum;
    }
    if (tid < 8) {
        float m1 = -FLT_MAX, m2 = -FLT_MAX;
        #pragma unroll
        for (int s = 0; s < 4; s++) {
            float v = ilog_s[tid * 4 + s];
            if (v > m1) { m2 = m1; m1 = v; } else if (v > m2) m2 = v;
        }
        float ex[4]; float sum = 0.f;
        #pragma unroll
        for (int s = 0; s < 4; s++) {
            float v = ilog_s[tid * 4 + s];
            if (v >= m2) { ex[s] = expf(v - m1); sum += ex[s]; } else ex[s] = 0.f;
        }
        #pragma unroll
        for (int s = 0; s < 4; s++) cw_s[tid * 4 + s] = ex[s] / sum;
    }
    __syncthreads();
    if (tid < 32) w_s[tid] = gw_s[tid >> 2] * cw_s[tid];
    __syncthreads();

    #pragma unroll
    for (int d = tid; d < 512; d += 256) {
        float a = 0.f;
        #pragma unroll
        for (int e = 0; e < 32; e++) a += w_s[e] * be2[e * 512 + d];
        y[(size_t)t * 512 + d] = a;
    }

    if (tid < 32 && w_s[tid] > 0.f) {
        int pos = atomicAdd(&g_cnt[tid], 1);
        g_tok[tid * NTOK + pos] = t;
        g_wt [tid * NTOK + pos] = w_s[tid];
    }
}

// ---------------- K3: expert FFN via fp16 mma m16n8k16 ----------------
// Block: 64 tokens, 8 warps = 2(M)x4(N), warp tile 32x64.
// All operand smem in half2 (uint) with conflict-free pitches:
//   Xs2  pitch 20  (16 data + 4 pad)   [64 rows]
//   Ws2  pitch 264 (256 data + 8 pad)  [16 k-pair rows]
//   H1s2 pitch 132 (128 data + 4 pad)  [64 rows]
#define XP2 20
#define WP2 264
#define HP2 132
#define OFF_TOK   0
#define OFF_WT    64
#define OFF_BIAS  128
#define OFF_XS    384
#define OFF_WS    (OFF_XS + 64*XP2)          // 1664
#define OFF_H1    (OFF_WS + 16*WP2)          // 5888
#define SMEM_WORDS (OFF_H1 + 64*HP2)         // 14336
#define SMEM_BYTES (SMEM_WORDS * 4)

__global__ __launch_bounds__(256) void k_expert_mma(
    const float* __restrict__ H,
    const float* __restrict__ We1, const float* __restrict__ be1,
    const float* __restrict__ We2, float* __restrict__ y)
{
    extern __shared__ uint32_t smu[];
    int*      tok_s  = (int*)smu;
    float*    wt_s   = (float*)(smu + OFF_WT);
    float*    bias_s = (float*)(smu + OFF_BIAS);
    uint32_t* Xs2    = smu + OFF_XS;
    uint32_t* Ws2    = smu + OFF_WS;
    uint32_t* H1s2   = smu + OFF_H1;

    const int e = blockIdx.x;
    const int n = g_cnt[e];
    const int base = blockIdx.y * 64;
    if (base >= n) return;

    const int tid  = threadIdx.x;
    const int w    = tid >> 5;
    const int lane = tid & 31;
    const int gid  = lane >> 2;
    const int tig  = lane & 3;
    const int mwarp = (w & 1) * 32;
    const int nwarp = (w >> 1) * 64;

    if (tid < 64) {
        int idx = base + tid;
        if (idx < n) { tok_s[tid] = g_tok[e * NTOK + idx]; wt_s[tid] = g_wt[e * NTOK + idx]; }
        else         { tok_s[tid] = g_tok[e * NTOK + base]; wt_s[tid] = 0.f; }
    }
    bias_s[tid] = be1[e * 256 + tid];
    __syncthreads();

    // staging coords
    const int wkk = tid >> 6;             // 0..3 (k-pair row offset within group of 4)
    const int wn4 = (tid & 63) * 4;       // n base (4 cols)

    float acc[2][8][4];
    float4 wbufA[4], wbufB[4];
    float2 xbuf[4];

    // ================= phase 1: h1 = gelu(X[64,512] @ We1[512,256] + b) =================
    #pragma unroll
    for (int m8 = 0; m8 < 2; m8++)
        #pragma unroll
        for (int n8 = 0; n8 < 8; n8++)
            #pragma unroll
            for (int c = 0; c < 4; c++) acc[m8][n8][c] = 0.f;

    const float* W1 = We1 + (size_t)e * 512 * 256;

    // prefetch chunk 0
    #pragma unroll
    for (int i = 0; i < 4; i++) {
        int idx = i * 256 + tid;
        int t = idx >> 4, kk = idx & 15;
        xbuf[i] = *(const float2*)&H[(size_t)tok_s[t] * 512 + 2 * kk];
        int kr = i * 4 + wkk;
        wbufA[i] = *(const float4*)&W1[(size_t)(2 * kr)     * 256 + wn4];
        wbufB[i] = *(const float4*)&W1[(size_t)(2 * kr + 1) * 256 + wn4];
    }

    for (int kc = 0; kc < 512; kc += 32) {
        // commit prefetched chunk to smem (convert to half2)
        #pragma unroll
        for (int i = 0; i < 4; i++) {
            int idx = i * 256 + tid;
            int t = idx >> 4, kk = idx & 15;
            Xs2[t * XP2 + kk] = pack_h2(xbuf[i].x, xbuf[i].y);
            int kr = i * 4 + wkk;
            uint32_t* dst = &Ws2[kr * WP2 + wn4];
            dst[0] = pack_h2(wbufA[i].x, wbufB[i].x);
            dst[1] = pack_h2(wbufA[i].y, wbufB[i].y);
            dst[2] = pack_h2(wbufA[i].z, wbufB[i].z);
            dst[3] = pack_h2(wbufA[i].w, wbufB[i].w);
        }
        __syncthreads();

        // prefetch next chunk
        if (kc + 32 < 512) {
            #pragma unroll
            for (int i = 0; i < 4; i++) {
                int idx = i * 256 + tid;
                int t = idx >> 4, kk = idx & 15;
                xbuf[i] = *(const float2*)&H[(size_t)tok_s[t] * 512 + kc + 32 + 2 * kk];
                int kr = i * 4 + wkk;
                wbufA[i] = *(const float4*)&W1[(size_t)(kc + 32 + 2 * kr)     * 256 + wn4];
                wbufB[i] = *(const float4*)&W1[(size_t)(kc + 32 + 2 * kr + 1) * 256 + wn4];
            }
        }

        #pragma unroll
        for (int ks = 0; ks < 2; ks++) {
            const int kh = ks * 8;
            uint32_t a[2][4];
            #pragma unroll
            for (int m8 = 0; m8 < 2; m8++) {
                int r0 = mwarp + m8 * 16 + gid;
                a[m8][0] = Xs2[r0 * XP2 + kh + tig];
                a[m8][1] = Xs2[(r0 + 8) * XP2 + kh + tig];
                a[m8][2] = Xs2[r0 * XP2 + kh + tig + 4];
                a[m8][3] = Xs2[(r0 + 8) * XP2 + kh + tig + 4];
            }
            #pragma unroll
            for (int n8 = 0; n8 < 8; n8++) {
                int ncol = nwarp + n8 * 8 + gid;
                uint32_t b0 = Ws2[(kh + tig) * WP2 + ncol];
                uint32_t b1 = Ws2[(kh + tig + 4) * WP2 + ncol];
                mma16(acc[0][n8], a[0], b0, b1);
                mma16(acc[1][n8], a[1], b0, b1);
            }
        }
        __syncthreads();
    }

    // epilogue 1: bias + gelu -> H1s2 (half2 per col pair)
    #pragma unroll
    for (int m8 = 0; m8 < 2; m8++) {
        #pragma unroll
        for (int c2 = 0; c2 < 2; c2++) {
            int row = mwarp + m8 * 16 + gid + (c2 ? 8 : 0);
            #pragma unroll
            for (int n8 = 0; n8 < 8; n8++) {
                int col0 = nwarp + n8 * 8 + 2 * tig;
                float v0 = gelu_exact(acc[m8][n8][c2 * 2 + 0] + bias_s[col0]);
                float v1 = gelu_exact(acc[m8][n8][c2 * 2 + 1] + bias_s[col0 + 1]);
                H1s2[row * HP2 + (col0 >> 1)] = pack_h2(v0, v1);
            }
        }
    }
    __syncthreads();

    // ================= phase 2: y += w * (h1[64,256] @ We2[256,512]) =================
    const float* W2 = We2 + (size_t)e * 256 * 512;
    #pragma unroll
    for (int half = 0; half < 2; half++) {
        #pragma unroll
        for (int m8 = 0; m8 < 2; m8++)
            #pragma unroll
            for (int n8 = 0; n8 < 8; n8++)
                #pragma unroll
                for (int c = 0; c < 4; c++) acc[m8][n8][c] = 0.f;

        // prefetch chunk 0
        #pragma unroll
        for (int i = 0; i < 4; i++) {
            int kr = i * 4 + wkk;
            wbufA[i] = *(const float4*)&W2[(size_t)(2 * kr)     * 512 + half * 256 + wn4];
            wbufB[i] = *(const float4*)&W2[(size_t)(2 * kr + 1) * 512 + half * 256 + wn4];
        }

        for (int kc = 0; kc < 256; kc += 32) {
            #pragma unroll
            for (int i = 0; i < 4; i++) {
                int kr = i * 4 + wkk;
                uint32_t* dst = &Ws2[kr * WP2 + wn4];
                dst[0] = pack_h2(wbufA[i].x, wbufB[i].x);
                dst[1] = pack_h2(wbufA[i].y, wbufB[i].y);
                dst[2] = pack_h2(wbufA[i].z, wbufB[i].z);
                dst[3] = pack_h2(wbufA[i].w, wbufB[i].w);
            }
            __syncthreads();

            if (kc + 32 < 256) {
                #pragma unroll
                for (int i = 0; i < 4; i++) {
                    int kr = i * 4 + wkk;
                    wbufA[i] = *(const float4*)&W2[(size_t)(kc + 32 + 2 * kr)     * 512 + half * 256 + wn4];
                    wbufB[i] = *(const float4*)&W2[(size_t)(kc + 32 + 2 * kr + 1) * 512 + half * 256 + wn4];
                }
            }

            #pragma unroll
            for (int ks = 0; ks < 2; ks++) {
                const int kh = ks * 8;
                const int ah = (kc >> 1) + kh;   // half2 col index into H1s2
                uint32_t a[2][4];
                #pragma unroll
                for (int m8 = 0; m8 < 2; m8++) {
                    int r0 = mwarp + m8 * 16 + gid;
                    a[m8][0] = H1s2[r0 * HP2 + ah + tig];
                    a[m8][1] = H1s2[(r0 + 8) * HP2 + ah + tig];
                    a[m8][2] = H1s2[r0 * HP2 + ah + tig + 4];
                    a[m8][3] = H1s2[(r0 + 8) * HP2 + ah + tig + 4];
                }
                #pragma unroll
                for (int n8 = 0; n8 < 8; n8++) {
                    int ncol = nwarp + n8 * 8 + gid;
                    uint32_t b0 = Ws2[(kh + tig) * WP2 + ncol];
                    uint32_t b1 = Ws2[(kh + tig + 4) * WP2 + ncol];
                    mma16(acc[0][n8], a[0], b0, b1);
                    mma16(acc[1][n8], a[1], b0, b1);
                }
            }
            __syncthreads();
        }

        // epilogue 2: scaled atomic accumulate
        #pragma unroll
        for (int m8 = 0; m8 < 2; m8++) {
            #pragma unroll
            for (int c2 = 0; c2 < 2; c2++) {
                int row = mwarp + m8 * 16 + gid + (c2 ? 8 : 0);
                float wgt = wt_s[row];
                if (wgt == 0.f) continue;
                int tok = tok_s[row];
                #pragma unroll
                for (int n8 = 0; n8 < 8; n8++) {
                    int col = half * 256 + nwarp + n8 * 8 + 2 * tig;
                    atomicAdd(&y[(size_t)tok * 512 + col],     wgt * acc[m8][n8][c2 * 2 + 0]);
                    atomicAdd(&y[(size_t)tok * 512 + col + 1], wgt * acc[m8][n8][c2 * 2 + 1]);
                }
            }
        }
    }
}

// ---------------- launch ----------------
extern "C" void kernel_launch(void* const* d_in, const int* in_sizes, int n_in,
                              void* d_out, int out_size) {
    (void)in_sizes; (void)n_in; (void)out_size;
    const float* hidden = (const float*)d_in[0];
    const float* feat   = (const float*)d_in[1];
    const float* Wr1    = (const float*)d_in[3];
    const float* br1    = (const float*)d_in[4];
    const float* Wr2    = (const float*)d_in[5];
    const float* br2    = (const float*)d_in[6];
    const float* Wfe    = (const float*)d_in[7];
    const float* bfe    = (const float*)d_in[8];
    const float* Win_h  = (const float*)d_in[9];
    const float* Win_f  = (const float*)d_in[10];
    const float* bin_b  = (const float*)d_in[11];
    const float* We1    = (const float*)d_in[12];
    const float* be1    = (const float*)d_in[13];
    const float* We2    = (const float*)d_in[14];
    const float* be2    = (const float*)d_in[15];
    float* y = (float*)d_out;

    static bool attr_set = false;
    if (!attr_set) {
        cudaFuncSetAttribute(k_expert_mma, cudaFuncAttributeMaxDynamicSharedMemorySize, SMEM_BYTES);
        attr_set = true;
    }

    k_reset<<<1, 32>>>();
    k_minmax<<<64, 256>>>(feat, NTOK * 32);
    k_gemm1<<<NTOK / 32, 256>>>(hidden, Wr1, br1, Win_h);
    k_route<<<NTOK, 256>>>(feat, Wr2, br2, Wfe, bfe,
                           Win_f, bin_b, be2, y);
    k_expert_mma<<<dim3(E_, NTOK / 64), 256, SMEM_BYTES>>>(hidden, We1, be1, We2, y);
}

// round 5
// speedup vs baseline: 2.4851x; 1.0625x over previous
#include <cuda_runtime.h>
#include <cuda_fp16.h>
#include <math.h>
#include <float.h>
#include <stdint.h>

#define NTOK 4096
#define DIM  512
#define RH_  256
#define E_   32
#define SHARP_ 16.0f

// ---------------- scratch ----------------
__device__ float    g_GH[NTOK * RH_];
__device__ float    g_IL[NTOK * E_];
__device__ int      g_cnt[E_];
__device__ int      g_tok[E_ * NTOK];
__device__ float    g_wt [E_ * NTOK];
__device__ unsigned g_minenc, g_maxenc;
__device__ float    g_M[128];   // M[g][f][s]
__device__ float    g_C[32];    // C[g][s]
// fp16 pre-converted operands (half2 packed as uint32)
__device__ uint32_t g_We1h[E_ * 65536];   // [e][kr0..255][n0..255]  (W[2kr][n],W[2kr+1][n])
__device__ uint32_t g_We2h[E_ * 65536];   // [e][kr0..127][n0..511]
__device__ uint32_t g_Hh  [NTOK * 256];   // [t][kk0..255] (H[t][2kk],H[t][2kk+1])

__device__ __forceinline__ unsigned encf(float x) {
    unsigned u = __float_as_uint(x);
    return (u & 0x80000000u) ? ~u : (u | 0x80000000u);
}
__device__ __forceinline__ float decf(unsigned e) {
    return (e & 0x80000000u) ? __uint_as_float(e ^ 0x80000000u)
                             : __uint_as_float(~e);
}
__device__ __forceinline__ float gelu_exact(float x) {
    return 0.5f * x * (1.0f + erff(x * 0.70710678118654752f));
}
__device__ __forceinline__ uint32_t pack_h2(float a, float b) {
    __half2 h = __floats2half2_rn(a, b);
    return *(uint32_t*)&h;
}
__device__ __forceinline__ void mma16(float* c, const uint32_t* a, uint32_t b0, uint32_t b1) {
    asm volatile(
        "mma.sync.aligned.m16n8k16.row.col.f32.f16.f16.f32 "
        "{%0,%1,%2,%3},{%4,%5,%6,%7},{%8,%9},{%0,%1,%2,%3};"
        : "+f"(c[0]), "+f"(c[1]), "+f"(c[2]), "+f"(c[3])
        : "r"(a[0]), "r"(a[1]), "r"(a[2]), "r"(a[3]), "r"(b0), "r"(b1));
}
__device__ __forceinline__ void cp_async16(uint32_t saddr, const void* g) {
    asm volatile("cp.async.ca.shared.global [%0], [%1], 16;" :: "r"(saddr), "l"(g));
}
__device__ __forceinline__ void cp_async8(uint32_t saddr, const void* g) {
    asm volatile("cp.async.ca.shared.global [%0], [%1], 8;" :: "r"(saddr), "l"(g));
}
__device__ __forceinline__ void cp_commit() { asm volatile("cp.async.commit_group;"); }
template<int N> __device__ __forceinline__ void cp_wait() {
    asm volatile("cp.async.wait_group %0;" :: "n"(N));
}

// ---------------- K0a: reset ----------------
__global__ void k_reset() {
    int i = threadIdx.x;
    if (i < E_) g_cnt[i] = 0;
    if (i == 0) { g_minenc = 0xFFFFFFFFu; g_maxenc = 0u; }
}

// ---------------- K0b: feat global min/max ----------------
__global__ void k_minmax(const float* __restrict__ feat, int n) {
    unsigned lmin = 0xFFFFFFFFu, lmax = 0u;
    for (int i = blockIdx.x * blockDim.x + threadIdx.x; i < n; i += gridDim.x * blockDim.x) {
        unsigned e = encf(feat[i]);
        lmin = min(lmin, e); lmax = max(lmax, e);
    }
    #pragma unroll
    for (int o = 16; o; o >>= 1) {
        lmin = min(lmin, __shfl_down_sync(0xFFFFFFFFu, lmin, o));
        lmax = max(lmax, __shfl_down_sync(0xFFFFFFFFu, lmax, o));
    }
    if ((threadIdx.x & 31) == 0) {
        atomicMin(&g_minenc, lmin);
        atomicMax(&g_maxenc, lmax);
    }
}

// ---------------- K0c: routing-algebra precompute ----------------
__global__ void k_prep(const float* __restrict__ Wfe, const float* __restrict__ bfe,
                       const float* __restrict__ Win_f) {
    int tid = threadIdx.x;
    if (tid < 128) {
        int g = tid >> 4, f = (tid >> 2) & 3, s = tid & 3;
        float acc = 0.f;
        #pragma unroll 4
        for (int e = 0; e < 64; e++)
            acc += Wfe[(g * 4 + f) * 64 + e] * Win_f[(g * 64 + e) * 4 + s];
        g_M[tid] = acc;
    } else if (tid < 160) {
        int j = tid - 128; int g = j >> 2, s = j & 3;
        float acc = 0.f;
        #pragma unroll 4
        for (int e = 0; e < 64; e++)
            acc += bfe[g * 64 + e] * Win_f[(g * 64 + e) * 4 + s];
        g_C[j] = acc;
    }
}

// ---------------- conversion kernels ----------------
__global__ __launch_bounds__(256) void k_cvt_h(const float* __restrict__ H) {
    int id = blockIdx.x * 256 + threadIdx.x;      // 262144 threads
    int t = id >> 6, p = id & 63;
    const float4* src = (const float4*)&H[(size_t)t * 512 + p * 8];
    float4 a = src[0], b = src[1];
    uint4 o;
    o.x = pack_h2(a.x, a.y); o.y = pack_h2(a.z, a.w);
    o.z = pack_h2(b.x, b.y); o.w = pack_h2(b.z, b.w);
    ((uint4*)g_Hh)[(size_t)t * 64 + p] = o;
}
__global__ __launch_bounds__(256) void k_cvt_w1(const float* __restrict__ We1) {
    int id = blockIdx.x * 256 + threadIdx.x;      // 524288 threads
    int e = id >> 14, rem = id & 16383;
    int kr = rem >> 6, n = (rem & 63) * 4;
    const float* base = We1 + ((size_t)e * 512 + 2 * kr) * 256 + n;
    float4 a = *(const float4*)base;
    float4 b = *(const float4*)(base + 256);
    uint4 o;
    o.x = pack_h2(a.x, b.x); o.y = pack_h2(a.y, b.y);
    o.z = pack_h2(a.z, b.z); o.w = pack_h2(a.w, b.w);
    ((uint4*)g_We1h)[((size_t)e * 65536 + kr * 256 + n) >> 2] = o;
}
__global__ __launch_bounds__(256) void k_cvt_w2(const float* __restrict__ We2) {
    int id = blockIdx.x * 256 + threadIdx.x;      // 524288 threads
    int e = id >> 14, rem = id & 16383;
    int kr = rem >> 7, n = (rem & 127) * 4;
    const float* base = We2 + ((size_t)e * 256 + 2 * kr) * 512 + n;
    float4 a = *(const float4*)base;
    float4 b = *(const float4*)(base + 512);
    uint4 o;
    o.x = pack_h2(a.x, b.x); o.y = pack_h2(a.y, b.y);
    o.z = pack_h2(a.z, b.z); o.w = pack_h2(a.w, b.w);
    ((uint4*)g_We2h)[((size_t)e * 65536 + kr * 512 + n) >> 2] = o;
}

// ---------------- K1: GH = gelu(H @ Wr1 + br1)  +  IL = H @ Win_h (fp32) ----------------
__global__ __launch_bounds__(256) void k_gemm1(const float* __restrict__ H,
                                               const float* __restrict__ Wr1,
                                               const float* __restrict__ br1,
                                               const float* __restrict__ Win_h) {
    __shared__ __align__(16) float Xs[64][36];
    const int h = threadIdx.x;
    const int base = blockIdx.x * 32;
    const int tI = h >> 3;
    const int gI = h & 7;
    float acc[32];
    float4 acc2 = make_float4(0.f, 0.f, 0.f, 0.f);
    #pragma unroll
    for (int t = 0; t < 32; t++) acc[t] = 0.f;

    for (int kc = 0; kc < DIM; kc += 64) {
        #pragma unroll
        for (int it = 0; it < 8; it++) {
            int idx = it * 256 + h;
            int t = idx >> 6, j = idx & 63;
            Xs[j][t] = H[(size_t)(base + t) * DIM + kc + j];
        }
        __syncthreads();
        #pragma unroll 8
        for (int d = 0; d < 64; d++) {
            float wv = Wr1[(size_t)(kc + d) * RH_ + h];
            const float4* xr = (const float4*)Xs[d];
            #pragma unroll
            for (int q = 0; q < 8; q++) {
                float4 xv = xr[q];
                acc[4*q+0] += xv.x * wv; acc[4*q+1] += xv.y * wv;
                acc[4*q+2] += xv.z * wv; acc[4*q+3] += xv.w * wv;
            }
        }
        #pragma unroll 4
        for (int d = 0; d < 64; d++) {
            float xv = Xs[d][tI];
            float4 wv = *(const float4*)&Win_h[gI * 2048 + (kc + d) * 4];
            acc2.x += xv * wv.x; acc2.y += xv * wv.y;
            acc2.z += xv * wv.z; acc2.w += xv * wv.w;
        }
        __syncthreads();
    }
    float b = br1[h];
    #pragma unroll
    for (int t = 0; t < 32; t++)
        g_GH[(size_t)(base + t) * RH_ + h] = gelu_exact(acc[t] + b);
    *(float4*)&g_IL[(size_t)(base + tI) * 32 + gI * 4] = acc2;
}

// ---------------- K2: per-token routing (light) ----------------
__global__ __launch_bounds__(256) void k_route(
    const float* __restrict__ feat,
    const float* __restrict__ Wr2, const float* __restrict__ br2,
    const float* __restrict__ bin_b,
    float* __restrict__ y)
{
    __shared__ float ghs[256], feat_s[32];
    __shared__ float glog_s[8], ilog_s[32], score_s[8], gw_s[8], cw_s[32], w_s[32];

    const int t = blockIdx.x, tid = threadIdx.x;
    const int wid = tid >> 5, lane = tid & 31;

    ghs[tid] = g_GH[(size_t)t * 256 + tid];
    if (tid < 32) feat_s[tid] = feat[(size_t)t * 32 + tid];
    __syncthreads();

    // glog[g]: warp g does 256-dot
    {
        float p = 0.f;
        #pragma unroll
        for (int k = 0; k < 8; k++) {
            int i = lane + 32 * k;
            p += ghs[i] * Wr2[i * 8 + wid];
        }
        #pragma unroll
        for (int o = 16; o; o >>= 1) p += __shfl_down_sync(0xFFFFFFFFu, p, o);
        if (lane == 0) glog_s[wid] = p + br2[wid];
    }

    const bool in01 = (decf(g_minenc) >= -1e-6f) && (decf(g_maxenc) <= 1.0f + 1e-6f);
    if (tid < 8) {
        float sc = 0.f;
        #pragma unroll
        for (int f = 0; f < 4; f++) {
            float x = feat_s[tid * 4 + f];
            float r = in01 ? fminf(fmaxf(x, 0.f), 1.f)
                           : fminf(fmaxf(0.5f * (1.f + erff(x * 0.70710678118654752f)), 0.f), 1.f);
            sc += r;
        }
        score_s[tid] = sc * 0.25f;
    }
    __syncthreads();

    // ilog[g][s] = IL + feat·M + C + bin_b + rule
    if (tid < 32) {
        int g = tid >> 2, s = tid & 3;
        float q = g_C[tid];
        #pragma unroll
        for (int f = 0; f < 4; f++)
            q += feat_s[g * 4 + f] * g_M[g * 16 + f * 4 + s];
        float c = (float)s * (1.0f / 3.0f);
        float dd = score_s[g] - c;
        ilog_s[tid] = q + g_IL[(size_t)t * 32 + tid] + bin_b[tid] - SHARP_ * dd * dd;
    }
    __syncthreads();

    if (tid == 0) {
        float m1 = -FLT_MAX, m2 = -FLT_MAX;
        #pragma unroll
        for (int g = 0; g < 8; g++) {
            float v = glog_s[g];
            if (v > m1) { m2 = m1; m1 = v; } else if (v > m2) m2 = v;
        }
        float ex[8]; float sum = 0.f;
        #pragma unroll
        for (int g = 0; g < 8; g++) {
            float v = glog_s[g];
            if (v >= m2) { ex[g] = expf(v - m1); sum += ex[g]; } else ex[g] = 0.f;
        }
        #pragma unroll
        for (int g = 0; g < 8; g++) gw_s[g] = ex[g] / sum;
    }
    if (tid < 8) {
        float m1 = -FLT_MAX, m2 = -FLT_MAX;
        #pragma unroll
        for (int s = 0; s < 4; s++) {
            float v = ilog_s[tid * 4 + s];
            if (v > m1) { m2 = m1; m1 = v; } else if (v > m2) m2 = v;
        }
        float ex[4]; float sum = 0.f;
        #pragma unroll
        for (int s = 0; s < 4; s++) {
            float v = ilog_s[tid * 4 + s];
            if (v >= m2) { ex[s] = expf(v - m1); sum += ex[s]; } else ex[s] = 0.f;
        }
        #pragma unroll
        for (int s = 0; s < 4; s++) cw_s[tid * 4 + s] = ex[s] / sum;
    }
    __syncthreads();
    if (tid < 32) w_s[tid] = gw_s[tid >> 2] * cw_s[tid];
    __syncthreads();

    // zero y (be2 handled in expert epilogue)
    ((float2*)&y[(size_t)t * 512])[tid] = make_float2(0.f, 0.f);

    if (tid < 32 && w_s[tid] > 0.f) {
        int pos = atomicAdd(&g_cnt[tid], 1);
        g_tok[tid * NTOK + pos] = t;
        g_wt [tid * NTOK + pos] = w_s[tid];
    }
}

// ---------------- K3: expert FFN, fp16 mma + cp.async double-buffer ----------------
#define XP2 20
#define WP2 264
#define HP2 132
#define XBUF (64 * XP2)          // 1280 words per X buffer
#define WBUF (16 * WP2)          // 4224 words per W buffer
#define OFF_TOK   0
#define OFF_WT    64
#define OFF_B1    128
#define OFF_B2    384
#define OFF_XS    896
#define OFF_WS    (OFF_XS + 2 * XBUF)     // 3456
#define OFF_H1    (OFF_WS + 2 * WBUF)     // 11904
#define SMEM_WORDS (OFF_H1 + 64 * HP2)    // 20352
#define SMEM_BYTES (SMEM_WORDS * 4)

__global__ __launch_bounds__(256, 2) void k_expert_mma(
    const float* __restrict__ be1, const float* __restrict__ be2,
    float* __restrict__ y)
{
    extern __shared__ uint32_t smu[];
    int*      tok_s  = (int*)smu;
    float*    wt_s   = (float*)(smu + OFF_WT);
    float*    bias_s = (float*)(smu + OFF_B1);
    float*    b2_s   = (float*)(smu + OFF_B2);
    uint32_t* Xs2    = smu + OFF_XS;
    uint32_t* Ws2    = smu + OFF_WS;
    uint32_t* H1s2   = smu + OFF_H1;

    const int e = blockIdx.x;
    const int n = g_cnt[e];
    const int base = blockIdx.y * 64;
    if (base >= n) return;

    const int tid  = threadIdx.x;
    const int w    = tid >> 5;
    const int lane = tid & 31;
    const int gid  = lane >> 2;
    const int tig  = lane & 3;
    const int mwarp = (w & 1) * 32;
    const int nwarp = (w >> 1) * 64;

    if (tid < 64) {
        int idx = base + tid;
        if (idx < n) { tok_s[tid] = g_tok[e * NTOK + idx]; wt_s[tid] = g_wt[e * NTOK + idx]; }
        else         { tok_s[tid] = g_tok[e * NTOK + base]; wt_s[tid] = 0.f; }
    }
    bias_s[tid] = be1[e * 256 + tid];
    b2_s[tid]       = be2[e * 512 + tid];
    b2_s[tid + 256] = be2[e * 512 + tid + 256];
    __syncthreads();

    const uint32_t xs_sb = (uint32_t)__cvta_generic_to_shared(Xs2);
    const uint32_t ws_sb = (uint32_t)__cvta_generic_to_shared(Ws2);
    const uint32_t* W1h = g_We1h + (size_t)e * 65536;
    const uint32_t* W2h = g_We2h + (size_t)e * 65536;

    // staging coords
    const int xt = tid >> 2, xp = (tid & 3) * 2;   // X: 2x8B per thread (t row, 8B unit)

    float acc[2][8][4];

    // ================= phase 1: h1 = gelu(X @ We1 + b1) =================
    #pragma unroll
    for (int m8 = 0; m8 < 2; m8++)
        #pragma unroll
        for (int n8 = 0; n8 < 8; n8++)
            #pragma unroll
            for (int c = 0; c < 4; c++) acc[m8][n8][c] = 0.f;

    // stage helpers expanded inline:
    #define STAGE_X(buf, kci) do { \
        _Pragma("unroll") \
        for (int j = 0; j < 2; j++) { \
            int t = xt + j * 64 / 2; /* placeholder, replaced below */ \
        } \
    } while(0)
    // (real staging below, written explicitly)

    // prologue: chunks 0,1
    #pragma unroll
    for (int pc = 0; pc < 2; pc++) {
        // X chunk pc: 64 rows x 16 words; thread does 2x 8B (units u = tid*2+j)
        #pragma unroll
        for (int j = 0; j < 2; j++) {
            int u = tid * 2 + j;
            int t = u >> 3, p = u & 7;
            cp_async8(xs_sb + (pc * XBUF + t * XP2 + p * 2) * 4,
                      &g_Hh[(size_t)tok_s[t] * 256 + pc * 16 + p * 2]);
        }
        // W chunk pc: 16 rows x 256 words; thread does 4x 16B
        #pragma unroll
        for (int j = 0; j < 4; j++) {
            int u = j * 256 + tid;
            int kr = u >> 6, c = (u & 63) * 4;
            cp_async16(ws_sb + (pc * WBUF + kr * WP2 + c) * 4,
                       &W1h[(pc * 16 + kr) * 256 + c]);
        }
        cp_commit();
    }

    for (int i = 0; i < 16; i++) {
        if (i < 15) cp_wait<1>(); else cp_wait<0>();
        __syncthreads();
        const uint32_t* Xb = Xs2 + (i & 1) * XBUF;
        const uint32_t* Wb = Ws2 + (i & 1) * WBUF;

        #pragma unroll
        for (int ks = 0; ks < 2; ks++) {
            const int kh = ks * 8;
            uint32_t a[2][4];
            #pragma unroll
            for (int m8 = 0; m8 < 2; m8++) {
                int r0 = mwarp + m8 * 16 + gid;
                a[m8][0] = Xb[r0 * XP2 + kh + tig];
                a[m8][1] = Xb[(r0 + 8) * XP2 + kh + tig];
                a[m8][2] = Xb[r0 * XP2 + kh + tig + 4];
                a[m8][3] = Xb[(r0 + 8) * XP2 + kh + tig + 4];
            }
            #pragma unroll
            for (int n8 = 0; n8 < 8; n8++) {
                int ncol = nwarp + n8 * 8 + gid;
                uint32_t b0 = Wb[(kh + tig) * WP2 + ncol];
                uint32_t b1 = Wb[(kh + tig + 4) * WP2 + ncol];
                mma16(acc[0][n8], a[0], b0, b1);
                mma16(acc[1][n8], a[1], b0, b1);
            }
        }
        __syncthreads();

        if (i + 2 < 16) {
            int kci = i + 2, buf = i & 1;
            #pragma unroll
            for (int j = 0; j < 2; j++) {
                int u = tid * 2 + j;
                int t = u >> 3, p = u & 7;
                cp_async8(xs_sb + (buf * XBUF + t * XP2 + p * 2) * 4,
                          &g_Hh[(size_t)tok_s[t] * 256 + kci * 16 + p * 2]);
            }
            #pragma unroll
            for (int j = 0; j < 4; j++) {
                int u = j * 256 + tid;
                int kr = u >> 6, c = (u & 63) * 4;
                cp_async16(ws_sb + (buf * WBUF + kr * WP2 + c) * 4,
                           &W1h[(kci * 16 + kr) * 256 + c]);
            }
            cp_commit();
        }
    }

    // epilogue 1: bias + gelu -> H1s2
    #pragma unroll
    for (int m8 = 0; m8 < 2; m8++) {
        #pragma unroll
        for (int c2 = 0; c2 < 2; c2++) {
            int row = mwarp + m8 * 16 + gid + (c2 ? 8 : 0);
            #pragma unroll
            for (int n8 = 0; n8 < 8; n8++) {
                int col0 = nwarp + n8 * 8 + 2 * tig;
                float v0 = gelu_exact(acc[m8][n8][c2 * 2 + 0] + bias_s[col0]);
                float v1 = gelu_exact(acc[m8][n8][c2 * 2 + 1] + bias_s[col0 + 1]);
                H1s2[row * HP2 + (col0 >> 1)] = pack_h2(v0, v1);
            }
        }
    }
    __syncthreads();

    // ================= phase 2: y += w * (h1 @ We2 + be2) =================
    #pragma unroll
    for (int half = 0; half < 2; half++) {
        #pragma unroll
        for (int m8 = 0; m8 < 2; m8++)
            #pragma unroll
            for (int n8 = 0; n8 < 8; n8++)
                #pragma unroll
                for (int c = 0; c < 4; c++) acc[m8][n8][c] = 0.f;

        // prologue: W chunks 0,1
        #pragma unroll
        for (int pc = 0; pc < 2; pc++) {
            #pragma unroll
            for (int j = 0; j < 4; j++) {
                int u = j * 256 + tid;
                int kr = u >> 6, c = (u & 63) * 4;
                cp_async16(ws_sb + (pc * WBUF + kr * WP2 + c) * 4,
                           &W2h[(size_t)(pc * 16 + kr) * 512 + half * 256 + c]);
            }
            cp_commit();
        }

        for (int i = 0; i < 8; i++) {
            if (i < 7) cp_wait<1>(); else cp_wait<0>();
            __syncthreads();
            const uint32_t* Wb = Ws2 + (i & 1) * WBUF;
            const int kc = i * 32;

            #pragma unroll
            for (int ks = 0; ks < 2; ks++) {
                const int kh = ks * 8;
                const int ah = (kc >> 1) + kh;
                uint32_t a[2][4];
                #pragma unroll
                for (int m8 = 0; m8 < 2; m8++) {
                    int r0 = mwarp + m8 * 16 + gid;
                    a[m8][0] = H1s2[r0 * HP2 + ah + tig];
                    a[m8][1] = H1s2[(r0 + 8) * HP2 + ah + tig];
                    a[m8][2] = H1s2[r0 * HP2 + ah + tig + 4];
                    a[m8][3] = H1s2[(r0 + 8) * HP2 + ah + tig + 4];
                }
                #pragma unroll
                for (int n8 = 0; n8 < 8; n8++) {
                    int ncol = nwarp + n8 * 8 + gid;
                    uint32_t b0 = Wb[(kh + tig) * WP2 + ncol];
                    uint32_t b1 = Wb[(kh + tig + 4) * WP2 + ncol];
                    mma16(acc[0][n8], a[0], b0, b1);
                    mma16(acc[1][n8], a[1], b0, b1);
                }
            }
            __syncthreads();

            if (i + 2 < 8) {
                int kci = i + 2, buf = i & 1;
                #pragma unroll
                for (int j = 0; j < 4; j++) {
                    int u = j * 256 + tid;
                    int kr = u >> 6, c = (u & 63) * 4;
                    cp_async16(ws_sb + (buf * WBUF + kr * WP2 + c) * 4,
                               &W2h[(size_t)(kci * 16 + kr) * 512 + half * 256 + c]);
                }
                cp_commit();
            }
        }

        // epilogue 2: y += w * (acc + be2)
        #pragma unroll
        for (int m8 = 0; m8 < 2; m8++) {
            #pragma unroll
            for (int c2 = 0; c2 < 2; c2++) {
                int row = mwarp + m8 * 16 + gid + (c2 ? 8 : 0);
                float wgt = wt_s[row];
                if (wgt == 0.f) continue;
                int tok = tok_s[row];
                #pragma unroll
                for (int n8 = 0; n8 < 8; n8++) {
                    int col = half * 256 + nwarp + n8 * 8 + 2 * tig;
                    atomicAdd(&y[(size_t)tok * 512 + col],
                              wgt * (acc[m8][n8][c2 * 2 + 0] + b2_s[col]));
                    atomicAdd(&y[(size_t)tok * 512 + col + 1],
                              wgt * (acc[m8][n8][c2 * 2 + 1] + b2_s[col + 1]));
                }
            }
        }
    }
}

// ---------------- launch ----------------
extern "C" void kernel_launch(void* const* d_in, const int* in_sizes, int n_in,
                              void* d_out, int out_size) {
    (void)in_sizes; (void)n_in; (void)out_size;
    const float* hidden = (const float*)d_in[0];
    const float* feat   = (const float*)d_in[1];
    const float* Wr1    = (const float*)d_in[3];
    const float* br1    = (const float*)d_in[4];
    const float* Wr2    = (const float*)d_in[5];
    const float* br2    = (const float*)d_in[6];
    const float* Wfe    = (const float*)d_in[7];
    const float* bfe    = (const float*)d_in[8];
    const float* Win_h  = (const float*)d_in[9];
    const float* Win_f  = (const float*)d_in[10];
    const float* bin_b  = (const float*)d_in[11];
    const float* We1    = (const float*)d_in[12];
    const float* be1    = (const float*)d_in[13];
    const float* We2    = (const float*)d_in[14];
    const float* be2    = (const float*)d_in[15];
    float* y = (float*)d_out;

    static bool attr_set = false;
    if (!attr_set) {
        cudaFuncSetAttribute(k_expert_mma, cudaFuncAttributeMaxDynamicSharedMemorySize, SMEM_BYTES);
        attr_set = true;
    }

    k_reset<<<1, 32>>>();
    k_minmax<<<64, 256>>>(feat, NTOK * 32);
    k_prep<<<1, 160>>>(Wfe, bfe, Win_f);
    k_cvt_h<<<NTOK / 4, 256>>>(hidden);
    k_cvt_w1<<<2048, 256>>>(We1);
    k_cvt_w2<<<2048, 256>>>(We2);
    k_gemm1<<<NTOK / 32, 256>>>(hidden, Wr1, br1, Win_h);
    k_route<<<NTOK, 256>>>(feat, Wr2, br2, bin_b, y);
    k_expert_mma<<<dim3(E_, NTOK / 64), 256, SMEM_BYTES>>>(be1, be2, y);
}